// round 11
// baseline (speedup 1.0000x reference)
#include <cuda_runtime.h>
#include <cuda_fp16.h>
#include <math.h>
#include <stdint.h>

// Problem constants
#define BATCH 4
#define T 1024
#define E 1024
#define NH 16
#define HS 64
#define HID 4096
#define M_ROWS (BATCH * T)   // 4096
#define LN_EPS 1e-5f
#define ATT_SCALE 0.03125f   // E^-0.25 on q and k each -> E^-0.5 on dot
#define LOG2E 1.4426950408889634f
#define MAX_CTAS 296         // 2 CTA/SM x 148 SMs

// ---------------------------------------------------------------------------
// Scratch (__device__ globals; no allocation allowed)
// ---------------------------------------------------------------------------
__device__ float  g_tmp[M_ROWS * E];
__device__ float  g_x1f[M_ROWS * E];
__device__ float  g_x2f[M_ROWS * E];
__device__ __half g_qh[M_ROWS * E], g_kh[M_ROWS * E], g_vh[M_ROWS * E];
__device__ __half g_ath[M_ROWS * E];
__device__ __half g_xh[M_ROWS * E];
__device__ __half g_ctxh[M_ROWS * E];
__device__ __half g_x1h[M_ROWS * E];
__device__ __half g_x2h[M_ROWS * E];
__device__ __half g_ffh[M_ROWS * HID];
// fp16 transposed weights [N,K] (QKV packed for fused projections)
__device__ __half g_wqkv_sa[3 * E * E];         // wq^T | wk^T | wv^T
__device__ __half g_wqkv_ca[3 * E * E];         // wq^T | wk^T | wv^T
__device__ __half g_sa_wot[E * E], g_ca_wot[E * E];
__device__ __half g_w1t[HID * E], g_w2t[E * HID];

// ---------------------------------------------------------------------------
// PTX helpers (sm_80+-compatible: cp.async, ldmatrix, mma.sync)
// ---------------------------------------------------------------------------
__device__ __forceinline__ uint32_t smem_u32(const void* p) {
    uint32_t a;
    asm("{ .reg .u64 t; cvta.to.shared.u64 t, %1; cvt.u32.u64 %0, t; }"
        : "=r"(a) : "l"(p));
    return a;
}

#define CP_ASYNC16(saddr, gptr) \
    asm volatile("cp.async.cg.shared.global [%0], [%1], 16;" \
        :: "r"(saddr), "l"(gptr) : "memory")
#define CP_COMMIT()  asm volatile("cp.async.commit_group;" ::: "memory")
#define CP_WAIT0()   asm volatile("cp.async.wait_group 0;" ::: "memory")
#define CP_WAIT1()   asm volatile("cp.async.wait_group 1;" ::: "memory")

#define LDSM4(r, addr) \
    asm volatile("ldmatrix.sync.aligned.m8n8.x4.shared.b16 {%0,%1,%2,%3}, [%4];" \
        : "=r"((r)[0]), "=r"((r)[1]), "=r"((r)[2]), "=r"((r)[3]) : "r"(addr))
#define LDSM2(r, addr) \
    asm volatile("ldmatrix.sync.aligned.m8n8.x2.shared.b16 {%0,%1}, [%2];" \
        : "=r"((r)[0]), "=r"((r)[1]) : "r"(addr))
#define LDSM4T(r, addr) \
    asm volatile("ldmatrix.sync.aligned.m8n8.x4.trans.shared.b16 {%0,%1,%2,%3}, [%4];" \
        : "=r"((r)[0]), "=r"((r)[1]), "=r"((r)[2]), "=r"((r)[3]) : "r"(addr))

__device__ __forceinline__ void mma16816(float* c, const uint32_t* a, const uint32_t* b) {
    asm volatile(
        "mma.sync.aligned.m16n8k16.row.col.f32.f16.f16.f32 "
        "{%0,%1,%2,%3}, {%4,%5,%6,%7}, {%8,%9}, {%0,%1,%2,%3};"
        : "+f"(c[0]), "+f"(c[1]), "+f"(c[2]), "+f"(c[3])
        : "r"(a[0]), "r"(a[1]), "r"(a[2]), "r"(a[3]), "r"(b[0]), "r"(b[1]));
}

// ===========================================================================
// Persistent single-plane HGEMM: C = A[M,K] @ Bt[N,K]^T (+bias)(+relu)
// grid = min(tiles, 296). Each CTA walks tiles t0, t0+G, ... with a
// continuous 3-stage cp.async ring across tile boundaries.
// - Tile coords updated incrementally ONCE per tile (no div/mod in k-loop).
// - Commit cadence uniform: one real commit per ktile (end-of-stream
//   prefetches re-load the current tile — harmless, no empty groups).
// - Uniform CP_WAIT1 (invariant: exactly 2 groups in flight after commit).
// A selected per N-tile: bx < a2Start -> Ah, else A2. Output: fp32 C32 OR
// fp16 into up to 3 dest buffers (bx/dstTiles, leading dim outLd).
// Tile 128x128x64, 256 threads (8 warps, 64x32 warp tile), 2 CTA/SM.
// ===========================================================================
#define HG1_STAGE 32768
#define HG1_SMEM  (3 * HG1_STAGE)

__global__ void __launch_bounds__(256, 2)
hgemm1_kernel(const __half* __restrict__ Ah, const __half* __restrict__ A2,
              int a2Start,
              const __half* __restrict__ Bt, const float* __restrict__ bias,
              float* __restrict__ C32,
              __half* __restrict__ D0, __half* __restrict__ D1, __half* __restrict__ D2,
              int dstTiles, int outLd, int N, int K, int relu,
              int NT_N, int numTiles)
{
    extern __shared__ char smem[];
    uint32_t sb = smem_u32(smem);
    int tid = threadIdx.x;
    int lane = tid & 31;
    int wid = tid >> 5;
    int wm = wid & 1, wn = wid >> 1;
    int G = gridDim.x;

    int lrow = tid >> 3;
    int lch = tid & 7;
    uint32_t soff[4];
#pragma unroll
    for (int i = 0; i < 4; i++) {
        int r = lrow + 32 * i;
        soff[i] = (uint32_t)(r * 128 + ((lch ^ (r & 7)) * 16));
    }

    uint32_t aOff[4], aX[4], bOff[4], bX[4];
#pragma unroll
    for (int mf = 0; mf < 4; mf++) {
        int r = wm * 64 + mf * 16 + (lane & 15);
        aOff[mf] = r * 128; aX[mf] = r & 7;
    }
#pragma unroll
    for (int nf = 0; nf < 4; nf++) {
        int r = wn * 32 + nf * 8 + (lane & 7);
        bOff[nf] = r * 128; bX[nf] = r & 7;
    }
    int aSel = lane >> 4;
    int bSel = (lane >> 3) & 1;

    float acc[4][4][4];
#pragma unroll
    for (int mf = 0; mf < 4; mf++)
#pragma unroll
        for (int nf = 0; nf < 4; nf++)
#pragma unroll
            for (int r = 0; r < 4; r++) acc[mf][nf][r] = 0.f;

    const int KT = K >> 6;
    int t = blockIdx.x;
    if (t >= numTiles) return;

    // Current tile coords
    int bx = t % NT_N, by = t / NT_N;
    const __half* gA = ((bx < a2Start) ? Ah : A2) + (size_t)by * 128 * K;
    const __half* gB = Bt + (size_t)bx * 128 * K;

    // Prologue: chunks 0,1 of first tile
#pragma unroll
    for (int p = 0; p < 2; p++) {
        uint32_t st = sb + p * HG1_STAGE;
        int k0 = p << 6;
#pragma unroll
        for (int i = 0; i < 4; i++) {
            int r = lrow + 32 * i;
            CP_ASYNC16(st + soff[i],         gA + (size_t)r * K + k0 + lch * 8);
            CP_ASYNC16(st + 16384 + soff[i], gB + (size_t)r * K + k0 + lch * 8);
        }
        CP_COMMIT();
    }

    int cur = 0, pf = 2;
    int g = lane >> 2, tig = lane & 3;

    while (true) {
        // Next tile coords (computed once per tile; clamp to current at end)
        int tn = t + G;
        const __half *gAn = gA, *gBn = gB;
        if (tn < numTiles) {
            int bxn = bx + G % NT_N + (G >= NT_N ? 0 : 0);
            int byn = by + G / NT_N;
            bxn = bx + (G % NT_N);
            if (bxn >= NT_N) { bxn -= NT_N; byn++; }
            gAn = ((bxn < a2Start) ? Ah : A2) + (size_t)byn * 128 * K;
            gBn = Bt + (size_t)bxn * 128 * K;
        }

        for (int kt = 0; kt < KT; kt++) {
            CP_WAIT1();
            __syncthreads();

            // Prefetch chunk kt+2 of this CTA's stream (wraps into next tile;
            // clamped to re-load current tile at the global end — uniform cadence)
            {
                const __half *pA, *pB; int k0;
                if (kt + 2 < KT) { pA = gA;  pB = gB;  k0 = (kt + 2) << 6; }
                else             { pA = gAn; pB = gBn; k0 = (kt + 2 - KT) << 6; }
                uint32_t st = sb + pf * HG1_STAGE;
#pragma unroll
                for (int i = 0; i < 4; i++) {
                    int r = lrow + 32 * i;
                    CP_ASYNC16(st + soff[i],         pA + (size_t)r * K + k0 + lch * 8);
                    CP_ASYNC16(st + 16384 + soff[i], pB + (size_t)r * K + k0 + lch * 8);
                }
                CP_COMMIT();
            }

            uint32_t aBase = sb + cur * HG1_STAGE;
            uint32_t bBase = aBase + 16384;

#pragma unroll
            for (int ks = 0; ks < 4; ks++) {
                int cA = ks * 2 + aSel;
                int cB = ks * 2 + bSel;
                uint32_t a[4][4], b[4][2];
#pragma unroll
                for (int mf = 0; mf < 4; mf++)
                    LDSM4(a[mf], aBase + aOff[mf] + ((cA ^ aX[mf]) << 4));
#pragma unroll
                for (int nf = 0; nf < 4; nf++)
                    LDSM2(b[nf], bBase + bOff[nf] + ((cB ^ bX[nf]) << 4));
#pragma unroll
                for (int mf = 0; mf < 4; mf++)
#pragma unroll
                    for (int nf = 0; nf < 4; nf++)
                        mma16816(acc[mf][nf], a[mf], b[nf]);
            }

            cur = (cur == 2) ? 0 : cur + 1;
            pf  = (pf == 2) ? 0 : pf + 1;
        }

        // Epilogue for tile t (overlaps in-flight prefetch of next tile)
        {
            int which = bx / dstTiles;
            int lbx = bx - which * dstTiles;
            __half* D = (which == 0) ? D0 : ((which == 1) ? D1 : D2);
#pragma unroll
            for (int mf = 0; mf < 4; mf++) {
#pragma unroll
                for (int nf = 0; nf < 4; nf++) {
                    int r0 = by * 128 + wm * 64 + mf * 16 + g;
                    int cl = wn * 32 + nf * 8 + tig * 2;
                    int cglob = bx * 128 + cl;
                    float b0 = 0.f, b1 = 0.f;
                    if (bias) { b0 = bias[cglob]; b1 = bias[cglob + 1]; }
                    float v0 = acc[mf][nf][0] + b0, v1 = acc[mf][nf][1] + b1;
                    float v2 = acc[mf][nf][2] + b0, v3 = acc[mf][nf][3] + b1;
                    if (relu) {
                        v0 = fmaxf(v0, 0.f); v1 = fmaxf(v1, 0.f);
                        v2 = fmaxf(v2, 0.f); v3 = fmaxf(v3, 0.f);
                    }
                    if (C32) {
                        *(float2*)(C32 + (size_t)r0 * N + cglob) = make_float2(v0, v1);
                        *(float2*)(C32 + (size_t)(r0 + 8) * N + cglob) = make_float2(v2, v3);
                    } else {
                        int c = lbx * 128 + cl;
                        *(__half2*)(D + (size_t)r0 * outLd + c) = __floats2half2_rn(v0, v1);
                        *(__half2*)(D + (size_t)(r0 + 8) * outLd + c) = __floats2half2_rn(v2, v3);
                    }
                    acc[mf][nf][0] = 0.f; acc[mf][nf][1] = 0.f;
                    acc[mf][nf][2] = 0.f; acc[mf][nf][3] = 0.f;
                }
            }
        }

        if (tn >= numTiles) break;
        t = tn;
        bx = bx + (G % NT_N);
        by = by + G / NT_N;
        if (bx >= NT_N) { bx -= NT_N; by++; }
        gA = ((bx < a2Start) ? Ah : A2) + (size_t)by * 128 * K;
        gB = Bt + (size_t)bx * 128 * K;
    }
}

// ---------------------------------------------------------------------------
// Tensor-core flash attention (R7 version — known good).
// grid (BATCH*NH, T/64), 128 threads. log2-domain softmax.
// ---------------------------------------------------------------------------
__global__ void __launch_bounds__(128)
fa_mma_kernel(const __half* __restrict__ Qm, const __half* __restrict__ Km,
              const __half* __restrict__ Vm, __half* __restrict__ Oh, int causal)
{
    __shared__ __half sQ[64 * 64];
    __shared__ __half sK[2][64 * 64];
    __shared__ __half sV[2][64 * 64];

    int tid = threadIdx.x, lane = tid & 31, w = tid >> 5;
    int g = lane >> 2, tig = lane & 3;
    int bh = blockIdx.x, b = bh >> 4, h = bh & 15;
    int qt = blockIdx.y;

    uint32_t sq = smem_u32(sQ);
    uint32_t skb[2] = { smem_u32(sK[0]), smem_u32(sK[1]) };
    uint32_t svb[2] = { smem_u32(sV[0]), smem_u32(sV[1]) };

    const __half* Qg = Qm + ((size_t)(b * T + qt * 64)) * E + h * HS;
    const __half* K0 = Km + ((size_t)(b * T)) * E + h * HS;
    const __half* V0 = Vm + ((size_t)(b * T)) * E + h * HS;

#pragma unroll
    for (int i = 0; i < 4; i++) {
        int c = tid + i * 128; int r = c >> 3; int ch = c & 7;
        uint32_t off = r * 128 + ((ch ^ (r & 7)) << 4);
        CP_ASYNC16(sq + off, Qg + (size_t)r * E + ch * 8);
        CP_ASYNC16(skb[0] + off, K0 + (size_t)r * E + ch * 8);
        CP_ASYNC16(svb[0] + off, V0 + (size_t)r * E + ch * 8);
    }
    CP_COMMIT();
    CP_WAIT0();
    __syncthreads();

    uint32_t qf[4][4];
    {
        int r = w * 16 + (lane & 15); int sel = lane >> 4; int rx = r & 7;
        uint32_t ro = sq + r * 128;
#pragma unroll
        for (int ks = 0; ks < 4; ks++)
            LDSM4(qf[ks], ro + (((2 * ks + sel) ^ rx) << 4));
    }

    float oacc[8][4];
#pragma unroll
    for (int n = 0; n < 8; n++)
#pragma unroll
        for (int e = 0; e < 4; e++) oacc[n][e] = 0.f;
    float m0 = -1e30f, m1 = -1e30f, l0 = 0.f, l1 = 0.f;

    int nk = causal ? (qt + 1) : (T / 64);
    const float SC2 = ATT_SCALE * LOG2E;   // scores in log2 domain

    for (int kt = 0; kt < nk; kt++) {
        int cur = kt & 1;
        if (kt + 1 < nk) {
            int nst = cur ^ 1;
            const __half* Kg = Km + ((size_t)(b * T + (kt + 1) * 64)) * E + h * HS;
            const __half* Vg = Vm + ((size_t)(b * T + (kt + 1) * 64)) * E + h * HS;
#pragma unroll
            for (int i = 0; i < 4; i++) {
                int c = tid + i * 128; int r = c >> 3; int ch = c & 7;
                uint32_t off = r * 128 + ((ch ^ (r & 7)) << 4);
                CP_ASYNC16(skb[nst] + off, Kg + (size_t)r * E + ch * 8);
                CP_ASYNC16(svb[nst] + off, Vg + (size_t)r * E + ch * 8);
            }
            CP_COMMIT();
        }

        float sacc[8][4];
#pragma unroll
        for (int n = 0; n < 8; n++)
#pragma unroll
            for (int e = 0; e < 4; e++) sacc[n][e] = 0.f;

        uint32_t skc = skb[cur], svc = svb[cur];
#pragma unroll
        for (int ks = 0; ks < 4; ks++) {
            uint32_t kb[8][2];
            int rl = lane & 7, sel = (lane >> 3) & 1;
#pragma unroll
            for (int n = 0; n < 8; n++) {
                int rr = n * 8 + rl;
                LDSM2(kb[n], skc + rr * 128 + (((2 * ks + sel) ^ (rr & 7)) << 4));
            }
#pragma unroll
            for (int n = 0; n < 8; n++) mma16816(sacc[n], qf[ks], kb[n]);
        }

#pragma unroll
        for (int n = 0; n < 8; n++)
#pragma unroll
            for (int e = 0; e < 4; e++) sacc[n][e] *= SC2;
        if (causal && kt == qt) {
            int row0 = w * 16 + g;
#pragma unroll
            for (int n = 0; n < 8; n++) {
                int c0 = n * 8 + tig * 2;
                if (c0     > row0)     sacc[n][0] = -1e30f;
                if (c0 + 1 > row0)     sacc[n][1] = -1e30f;
                if (c0     > row0 + 8) sacc[n][2] = -1e30f;
                if (c0 + 1 > row0 + 8) sacc[n][3] = -1e30f;
            }
        }

        float mx0 = -1e30f, mx1 = -1e30f;
#pragma unroll
        for (int n = 0; n < 8; n++) {
            mx0 = fmaxf(mx0, fmaxf(sacc[n][0], sacc[n][1]));
            mx1 = fmaxf(mx1, fmaxf(sacc[n][2], sacc[n][3]));
        }
        mx0 = fmaxf(mx0, __shfl_xor_sync(0xffffffffu, mx0, 1));
        mx0 = fmaxf(mx0, __shfl_xor_sync(0xffffffffu, mx0, 2));
        mx1 = fmaxf(mx1, __shfl_xor_sync(0xffffffffu, mx1, 1));
        mx1 = fmaxf(mx1, __shfl_xor_sync(0xffffffffu, mx1, 2));
        float mn0 = fmaxf(m0, mx0), mn1 = fmaxf(m1, mx1);
        float a0 = exp2f(m0 - mn0), a1 = exp2f(m1 - mn1);
        m0 = mn0; m1 = mn1;

        float ps0 = 0.f, ps1 = 0.f;
        uint32_t pfr[4][4];
#pragma unroll
        for (int n = 0; n < 8; n++) {
            float p0 = exp2f(sacc[n][0] - mn0), p1 = exp2f(sacc[n][1] - mn0);
            float p2 = exp2f(sacc[n][2] - mn1), p3 = exp2f(sacc[n][3] - mn1);
            ps0 += p0 + p1; ps1 += p2 + p3;
            __half2 h01 = __floats2half2_rn(p0, p1);
            __half2 h23 = __floats2half2_rn(p2, p3);
            int ks = n >> 1, hi = (n & 1) * 2;
            pfr[ks][hi]     = *(uint32_t*)&h01;
            pfr[ks][hi + 1] = *(uint32_t*)&h23;
        }
        l0 = l0 * a0 + ps0;
        l1 = l1 * a1 + ps1;
#pragma unroll
        for (int n = 0; n < 8; n++) {
            oacc[n][0] *= a0; oacc[n][1] *= a0;
            oacc[n][2] *= a1; oacc[n][3] *= a1;
        }

        {
            int rl = lane & 15, cs = lane >> 4;
#pragma unroll
            for (int np = 0; np < 4; np++) {
#pragma unroll
                for (int ks = 0; ks < 4; ks++) {
                    uint32_t vb[4];
                    int rr = ks * 16 + rl;
                    int ch = np * 2 + cs;
                    LDSM4T(vb, svc + rr * 128 + ((ch ^ (rr & 7)) << 4));
                    mma16816(oacc[2 * np],     pfr[ks], vb);
                    mma16816(oacc[2 * np + 1], pfr[ks], vb + 2);
                }
            }
        }

        CP_WAIT0();
        __syncthreads();
    }

    l0 += __shfl_xor_sync(0xffffffffu, l0, 1);
    l0 += __shfl_xor_sync(0xffffffffu, l0, 2);
    l1 += __shfl_xor_sync(0xffffffffu, l1, 1);
    l1 += __shfl_xor_sync(0xffffffffu, l1, 2);
    float i0 = 1.f / l0, i1 = 1.f / l1;

    size_t base0 = ((size_t)(b * T + qt * 64 + w * 16 + g)) * E + h * HS;
    size_t base1 = base0 + (size_t)8 * E;
#pragma unroll
    for (int n = 0; n < 8; n++) {
        int c = n * 8 + tig * 2;
        *(__half2*)(Oh + base0 + c) = __floats2half2_rn(oacc[n][0] * i0, oacc[n][1] * i0);
        *(__half2*)(Oh + base1 + c) = __floats2half2_rn(oacc[n][2] * i1, oacc[n][3] * i1);
    }
}

// ---------------------------------------------------------------------------
// Batched weight transpose to fp16 (8 equal E x E matrices, one launch)
// ---------------------------------------------------------------------------
struct TP8 { const float* s[8]; __half* d[8]; };

__global__ void __launch_bounds__(256)
transpose8_kernel(TP8 p)
{
    __shared__ float t[32][33];
    const float* in = p.s[blockIdx.z];
    __half* out = p.d[blockIdx.z];
    int bx = blockIdx.x * 32, by = blockIdx.y * 32;
    int x = threadIdx.x, y = threadIdx.y;
#pragma unroll
    for (int j = 0; j < 32; j += 8)
        t[y + j][x] = in[(size_t)(by + y + j) * E + bx + x];
    __syncthreads();
#pragma unroll
    for (int j = 0; j < 32; j += 8)
        out[(size_t)(bx + y + j) * E + by + x] = __float2half(t[x][y + j]);
}

// Batched transpose for the two FFN weights (z=0: w1 [E,HID]->[HID,E];
// z=1: w2 [HID,E]->[E,HID]).
__global__ void __launch_bounds__(256)
transpose_ff_kernel(const float* __restrict__ w1, __half* __restrict__ w1t,
                    const float* __restrict__ w2, __half* __restrict__ w2t)
{
    __shared__ float t[32][33];
    const float* in;  __half* out;  int R, C;
    if (blockIdx.z == 0) { in = w1; out = w1t; R = E;  C = HID; }
    else                 { in = w2; out = w2t; R = HID; C = E;  }
    int bx = blockIdx.x * 32, by = blockIdx.y * 32;
    if (bx >= C || by >= R) return;
    int x = threadIdx.x, y = threadIdx.y;
#pragma unroll
    for (int j = 0; j < 32; j += 8)
        t[y + j][x] = in[(size_t)(by + y + j) * C + bx + x];
    __syncthreads();
#pragma unroll
    for (int j = 0; j < 32; j += 8)
        out[(size_t)(bx + y + j) * R + by + x] = __float2half(t[x][y + j]);
}

// ---------------------------------------------------------------------------
// Dual fp32 -> fp16 convert (x and context), 4 float4s per thread
// ---------------------------------------------------------------------------
__global__ void __launch_bounds__(256)
conv2_h_kernel(const float* __restrict__ a, __half* __restrict__ ah,
               const float* __restrict__ b, __half* __restrict__ bh, int n)
{
    const float* src = blockIdx.y ? b : a;
    __half* dst = blockIdx.y ? bh : ah;
    int base = (blockIdx.x * 256 + threadIdx.x) * 4;
    int stride = gridDim.x * 256 * 4;
#pragma unroll
    for (int k = 0; k < 4; k++) {
        int i = base + k * stride;
        if (i < n) {
            float4 v = *(const float4*)(src + i);
            *(__half2*)(dst + i)     = __floats2half2_rn(v.x, v.y);
            *(__half2*)(dst + i + 2) = __floats2half2_rn(v.z, v.w);
        }
    }
}

// ---------------------------------------------------------------------------
// Fused residual + LayerNorm (+ optional fp16 plane), float4 I/O
// ---------------------------------------------------------------------------
__global__ void __launch_bounds__(256)
ln_residual_kernel(const float* __restrict__ X, const float* __restrict__ R,
                   const float* __restrict__ G, const float* __restrict__ Bt,
                   float* __restrict__ Out, __half* __restrict__ Oh)
{
    const int N = E;
    int row = blockIdx.x;
    int tid = threadIdx.x;
    int lane = tid & 31, wid = tid >> 5;
    __shared__ float sm[8];
    __shared__ float stats[2];

    int idx = tid * 4;
    float4 xv = *(const float4*)(X + (size_t)row * N + idx);
    float4 rv = *(const float4*)(R + (size_t)row * N + idx);
    float v0 = xv.x + rv.x, v1 = xv.y + rv.y, v2 = xv.z + rv.z, v3 = xv.w + rv.w;

    float s = (v0 + v1) + (v2 + v3);
#pragma unroll
    for (int off = 16; off > 0; off >>= 1) s += __shfl_down_sync(0xffffffffu, s, off);
    if (lane == 0) sm[wid] = s;
    __syncthreads();
    if (tid == 0) {
        float t = 0.f;
#pragma unroll
        for (int i = 0; i < 8; i++) t += sm[i];
        stats[0] = t * (1.f / N);
    }
    __syncthreads();
    float mu = stats[0];

    float d0 = v0 - mu, d1 = v1 - mu, d2 = v2 - mu, d3 = v3 - mu;
    float vs = (d0 * d0 + d1 * d1) + (d2 * d2 + d3 * d3);
#pragma unroll
    for (int off = 16; off > 0; off >>= 1) vs += __shfl_down_sync(0xffffffffu, vs, off);
    __syncthreads();
    if (lane == 0) sm[wid] = vs;
    __syncthreads();
    if (tid == 0) {
        float t = 0.f;
#pragma unroll
        for (int i = 0; i < 8; i++) t += sm[i];
        stats[1] = rsqrtf(t * (1.f / N) + LN_EPS);
    }
    __syncthreads();
    float rstd = stats[1];

    float4 gv = *(const float4*)(G + idx);
    float4 bv = *(const float4*)(Bt + idx);
    float y0 = d0 * rstd * gv.x + bv.x;
    float y1 = d1 * rstd * gv.y + bv.y;
    float y2 = d2 * rstd * gv.z + bv.z;
    float y3 = d3 * rstd * gv.w + bv.w;
    *(float4*)(Out + (size_t)row * N + idx) = make_float4(y0, y1, y2, y3);
    if (Oh) {
        *(__half2*)(Oh + (size_t)row * N + idx)     = __floats2half2_rn(y0, y1);
        *(__half2*)(Oh + (size_t)row * N + idx + 2) = __floats2half2_rn(y2, y3);
    }
}

// ---------------------------------------------------------------------------
// Launch
// ---------------------------------------------------------------------------
static inline int gmin(int a, int b) { return a < b ? a : b; }

extern "C" void kernel_launch(void* const* d_in, const int* in_sizes, int n_in,
                              void* d_out, int out_size)
{
    const float* x       = (const float*)d_in[0];
    const float* context = (const float*)d_in[1];
    const float* sa_wq = (const float*)d_in[2];
    const float* sa_wk = (const float*)d_in[3];
    const float* sa_wv = (const float*)d_in[4];
    const float* sa_wo = (const float*)d_in[5];
    const float* sa_bo = (const float*)d_in[6];
    const float* ca_wq = (const float*)d_in[7];
    const float* ca_wk = (const float*)d_in[8];
    const float* ca_wv = (const float*)d_in[9];
    const float* ca_wo = (const float*)d_in[10];
    const float* ca_bo = (const float*)d_in[11];
    const float* n1_g  = (const float*)d_in[12];
    const float* n1_b  = (const float*)d_in[13];
    const float* n2_g  = (const float*)d_in[14];
    const float* n2_b  = (const float*)d_in[15];
    const float* n3_g  = (const float*)d_in[16];
    const float* n3_b  = (const float*)d_in[17];
    const float* ff_w1 = (const float*)d_in[18];
    const float* ff_b1 = (const float*)d_in[19];
    const float* ff_w2 = (const float*)d_in[20];
    const float* ff_b2 = (const float*)d_in[21];
    float* out = (float*)d_out;

    float *tmp_, *x1f_, *x2f_;
    cudaGetSymbolAddress((void**)&tmp_, g_tmp);
    cudaGetSymbolAddress((void**)&x1f_, g_x1f);
    cudaGetSymbolAddress((void**)&x2f_, g_x2f);

    __half *qh, *kh, *vh, *ath;
    cudaGetSymbolAddress((void**)&qh,  g_qh);
    cudaGetSymbolAddress((void**)&kh,  g_kh);
    cudaGetSymbolAddress((void**)&vh,  g_vh);
    cudaGetSymbolAddress((void**)&ath, g_ath);

    __half *xh, *ctxh, *x1h, *x2h, *ffh;
    cudaGetSymbolAddress((void**)&xh,   g_xh);
    cudaGetSymbolAddress((void**)&ctxh, g_ctxh);
    cudaGetSymbolAddress((void**)&x1h,  g_x1h);
    cudaGetSymbolAddress((void**)&x2h,  g_x2h);
    cudaGetSymbolAddress((void**)&ffh,  g_ffh);

    __half *wqkv, *wqkvca, *wot, *cwot, *w1t, *w2t;
    cudaGetSymbolAddress((void**)&wqkv,   g_wqkv_sa);
    cudaGetSymbolAddress((void**)&wqkvca, g_wqkv_ca);
    cudaGetSymbolAddress((void**)&wot,    g_sa_wot);
    cudaGetSymbolAddress((void**)&cwot,   g_ca_wot);
    cudaGetSymbolAddress((void**)&w1t,    g_w1t);
    cudaGetSymbolAddress((void**)&w2t,    g_w2t);

    cudaFuncSetAttribute(hgemm1_kernel,
                         cudaFuncAttributeMaxDynamicSharedMemorySize, HG1_SMEM);

    // 8 E x E transposes in one launch
    TP8 tp;
    tp.s[0] = sa_wq; tp.d[0] = wqkv;
    tp.s[1] = sa_wk; tp.d[1] = wqkv + E * E;
    tp.s[2] = sa_wv; tp.d[2] = wqkv + 2 * E * E;
    tp.s[3] = sa_wo; tp.d[3] = wot;
    tp.s[4] = ca_wq; tp.d[4] = wqkvca;
    tp.s[5] = ca_wk; tp.d[5] = wqkvca + E * E;
    tp.s[6] = ca_wv; tp.d[6] = wqkvca + 2 * E * E;
    tp.s[7] = ca_wo; tp.d[7] = cwot;
    dim3 tB(32, 8);
    transpose8_kernel<<<dim3(E / 32, E / 32, 8), tB>>>(tp);
    transpose_ff_kernel<<<dim3(HID / 32, HID / 32, 2), tB>>>(ff_w1, w1t, ff_w2, w2t);

    int nElem = M_ROWS * E;
    conv2_h_kernel<<<dim3(nElem / 4096, 2), 256>>>(x, xh, context, ctxh, nElem);

    const int NT_M = M_ROWS / 128;        // 32
    int tQKV = (3 * E / 128) * NT_M;      // 768
    int tE   = (E / 128) * NT_M;          // 256
    int tH   = (HID / 128) * NT_M;        // 1024
    dim3 gFA(BATCH * NH, T / 64);

    // ---- Self-attention ----
    hgemm1_kernel<<<gmin(tQKV, MAX_CTAS), 256, HG1_SMEM>>>(
        xh, nullptr, 1 << 30, wqkv, nullptr, nullptr,
        qh, kh, vh, 8, E, 3 * E, E, 0, 3 * E / 128, tQKV);
    fa_mma_kernel<<<gFA, 128>>>(qh, kh, vh, ath, 1);
    hgemm1_kernel<<<gmin(tE, MAX_CTAS), 256, HG1_SMEM>>>(
        ath, nullptr, 1 << 30, wot, sa_bo, tmp_,
        nullptr, nullptr, nullptr, 8, E, E, E, 0, E / 128, tE);
    ln_residual_kernel<<<M_ROWS, 256>>>(x, tmp_, n1_g, n1_b, x1f_, x1h);

    // ---- Cross-attention (q from x1h, k/v from ctxh; one launch) ----
    hgemm1_kernel<<<gmin(tQKV, MAX_CTAS), 256, HG1_SMEM>>>(
        x1h, ctxh, 8, wqkvca, nullptr, nullptr,
        qh, kh, vh, 8, E, 3 * E, E, 0, 3 * E / 128, tQKV);
    fa_mma_kernel<<<gFA, 128>>>(qh, kh, vh, ath, 0);
    hgemm1_kernel<<<gmin(tE, MAX_CTAS), 256, HG1_SMEM>>>(
        ath, nullptr, 1 << 30, cwot, ca_bo, tmp_,
        nullptr, nullptr, nullptr, 8, E, E, E, 0, E / 128, tE);
    ln_residual_kernel<<<M_ROWS, 256>>>(x1f_, tmp_, n2_g, n2_b, x2f_, x2h);

    // ---- FFN ----
    hgemm1_kernel<<<gmin(tH, MAX_CTAS), 256, HG1_SMEM>>>(
        x2h, nullptr, 1 << 30, w1t, ff_b1, nullptr,
        ffh, nullptr, nullptr, 32, HID, HID, E, 1, HID / 128, tH);
    hgemm1_kernel<<<gmin(tE, MAX_CTAS), 256, HG1_SMEM>>>(
        ffh, nullptr, 1 << 30, w2t, ff_b2, tmp_,
        nullptr, nullptr, nullptr, 8, E, E, HID, 0, E / 128, tE);
    ln_residual_kernel<<<M_ROWS, 256>>>(x2f_, tmp_, n3_g, n3_b, out, nullptr);
}

// round 12
// speedup vs baseline: 1.0171x; 1.0171x over previous
#include <cuda_runtime.h>
#include <cuda_fp16.h>
#include <math.h>
#include <stdint.h>

// Problem constants
#define BATCH 4
#define T 1024
#define E 1024
#define NH 16
#define HS 64
#define HID 4096
#define M_ROWS (BATCH * T)   // 4096
#define LN_EPS 1e-5f
#define ATT_SCALE 0.03125f   // E^-0.25 on q and k each -> E^-0.5 on dot
#define LOG2E 1.4426950408889634f

// ---------------------------------------------------------------------------
// Scratch (__device__ globals; no allocation allowed)
// ---------------------------------------------------------------------------
__device__ float  g_x1f[M_ROWS * E];
__device__ float  g_x2f[M_ROWS * E];
__device__ __half g_tmph[M_ROWS * E];
__device__ __half g_qh[M_ROWS * E], g_kh[M_ROWS * E], g_vh[M_ROWS * E];
__device__ __half g_ath[M_ROWS * E];
__device__ __half g_xh[M_ROWS * E];
__device__ __half g_ctxh[M_ROWS * E];
__device__ __half g_x1h[M_ROWS * E];
__device__ __half g_x2h[M_ROWS * E];
__device__ __half g_ffh[M_ROWS * HID];
// fp16 transposed weights [N,K] (QKV packed for fused projections)
__device__ __half g_wqkv_sa[3 * E * E];         // wq^T | wk^T | wv^T
__device__ __half g_wqkv_ca[3 * E * E];         // wq^T | wk^T | wv^T
__device__ __half g_sa_wot[E * E], g_ca_wot[E * E];
__device__ __half g_w1t[HID * E], g_w2t[E * HID];

// ---------------------------------------------------------------------------
// PTX helpers (sm_80+-compatible: cp.async, ldmatrix, mma.sync)
// ---------------------------------------------------------------------------
__device__ __forceinline__ uint32_t smem_u32(const void* p) {
    uint32_t a;
    asm("{ .reg .u64 t; cvta.to.shared.u64 t, %1; cvt.u32.u64 %0, t; }"
        : "=r"(a) : "l"(p));
    return a;
}

#define CP_ASYNC16(saddr, gptr) \
    asm volatile("cp.async.cg.shared.global [%0], [%1], 16;" \
        :: "r"(saddr), "l"(gptr) : "memory")
#define CP_COMMIT()  asm volatile("cp.async.commit_group;" ::: "memory")
#define CP_WAIT0()   asm volatile("cp.async.wait_group 0;" ::: "memory")
#define CP_WAIT1()   asm volatile("cp.async.wait_group 1;" ::: "memory")

#define LDSM4(r, addr) \
    asm volatile("ldmatrix.sync.aligned.m8n8.x4.shared.b16 {%0,%1,%2,%3}, [%4];" \
        : "=r"((r)[0]), "=r"((r)[1]), "=r"((r)[2]), "=r"((r)[3]) : "r"(addr))
#define LDSM2(r, addr) \
    asm volatile("ldmatrix.sync.aligned.m8n8.x2.shared.b16 {%0,%1}, [%2];" \
        : "=r"((r)[0]), "=r"((r)[1]) : "r"(addr))
#define LDSM4T(r, addr) \
    asm volatile("ldmatrix.sync.aligned.m8n8.x4.trans.shared.b16 {%0,%1,%2,%3}, [%4];" \
        : "=r"((r)[0]), "=r"((r)[1]), "=r"((r)[2]), "=r"((r)[3]) : "r"(addr))

__device__ __forceinline__ void mma16816(float* c, const uint32_t* a, const uint32_t* b) {
    asm volatile(
        "mma.sync.aligned.m16n8k16.row.col.f32.f16.f16.f32 "
        "{%0,%1,%2,%3}, {%4,%5,%6,%7}, {%8,%9}, {%0,%1,%2,%3};"
        : "+f"(c[0]), "+f"(c[1]), "+f"(c[2]), "+f"(c[3])
        : "r"(a[0]), "r"(a[1]), "r"(a[2]), "r"(a[3]), "r"(b[0]), "r"(b[1]));
}

// ===========================================================================
// Single-plane HGEMM (R7 version — known good): C = A[M,K] @ Bt[N,K]^T
// (+bias)(+relu). A selected per N-tile: bx < a2Start -> Ah, else A2.
// Output: fp32 C32 OR fp16 into up to 3 dest buffers (bx/dstTiles, ld outLd).
// Tile 128x128x64, 256 threads, 3-stage cp.async (96KB smem, 2 CTA/SM),
// single __syncthreads per ktile.
// ===========================================================================
#define HG1_STAGE 32768
#define HG1_SMEM  (3 * HG1_STAGE)

__global__ void __launch_bounds__(256, 2)
hgemm1_kernel(const __half* __restrict__ Ah, const __half* __restrict__ A2,
              int a2Start,
              const __half* __restrict__ Bt, const float* __restrict__ bias,
              float* __restrict__ C32,
              __half* __restrict__ D0, __half* __restrict__ D1, __half* __restrict__ D2,
              int dstTiles, int outLd, int N, int K, int relu)
{
    extern __shared__ char smem[];
    uint32_t sb = smem_u32(smem);
    int tid = threadIdx.x;
    int lane = tid & 31;
    int wid = tid >> 5;
    int wm = wid & 1, wn = wid >> 1;
    int bx = blockIdx.x, by = blockIdx.y;

    const __half* Abase = (bx < a2Start) ? Ah : A2;
    const __half* gA = Abase + (size_t)by * 128 * K;
    const __half* gB = Bt + (size_t)bx * 128 * K;

    int lrow = tid >> 3;
    int lch = tid & 7;
    uint32_t soff[4];
#pragma unroll
    for (int i = 0; i < 4; i++) {
        int r = lrow + 32 * i;
        soff[i] = (uint32_t)(r * 128 + ((lch ^ (r & 7)) * 16));
    }

    uint32_t aOff[4], aX[4], bOff[4], bX[4];
#pragma unroll
    for (int mf = 0; mf < 4; mf++) {
        int r = wm * 64 + mf * 16 + (lane & 15);
        aOff[mf] = r * 128; aX[mf] = r & 7;
    }
#pragma unroll
    for (int nf = 0; nf < 4; nf++) {
        int r = wn * 32 + nf * 8 + (lane & 7);
        bOff[nf] = r * 128; bX[nf] = r & 7;
    }
    int aSel = lane >> 4;
    int bSel = (lane >> 3) & 1;

    float acc[4][4][4];
#pragma unroll
    for (int mf = 0; mf < 4; mf++)
#pragma unroll
        for (int nf = 0; nf < 4; nf++)
#pragma unroll
            for (int r = 0; r < 4; r++) acc[mf][nf][r] = 0.f;

    const int KT = K >> 6;

    // Prologue: stage ktiles 0 and 1 into buffers 0 and 1
#pragma unroll
    for (int p = 0; p < 2; p++) {
        uint32_t st = sb + p * HG1_STAGE;
        int k0 = p << 6;
#pragma unroll
        for (int i = 0; i < 4; i++) {
            int r = lrow + 32 * i;
            CP_ASYNC16(st + soff[i],         gA + (size_t)r * K + k0 + lch * 8);
            CP_ASYNC16(st + 16384 + soff[i], gB + (size_t)r * K + k0 + lch * 8);
        }
        CP_COMMIT();
    }

    int cur = 0;   // buffer for current ktile
    int pf = 2;    // buffer for ktile kt+2
    for (int kt = 0; kt < KT; kt++) {
        if (kt + 2 < KT) { CP_WAIT1(); } else { CP_WAIT0(); }
        __syncthreads();

        if (kt + 2 < KT) {
            uint32_t st = sb + pf * HG1_STAGE;
            int k0 = (kt + 2) << 6;
#pragma unroll
            for (int i = 0; i < 4; i++) {
                int r = lrow + 32 * i;
                CP_ASYNC16(st + soff[i],         gA + (size_t)r * K + k0 + lch * 8);
                CP_ASYNC16(st + 16384 + soff[i], gB + (size_t)r * K + k0 + lch * 8);
            }
            CP_COMMIT();
        }

        uint32_t aBase = sb + cur * HG1_STAGE;
        uint32_t bBase = aBase + 16384;

#pragma unroll
        for (int ks = 0; ks < 4; ks++) {
            int cA = ks * 2 + aSel;
            int cB = ks * 2 + bSel;
            uint32_t a[4][4], b[4][2];
#pragma unroll
            for (int mf = 0; mf < 4; mf++)
                LDSM4(a[mf], aBase + aOff[mf] + ((cA ^ aX[mf]) << 4));
#pragma unroll
            for (int nf = 0; nf < 4; nf++)
                LDSM2(b[nf], bBase + bOff[nf] + ((cB ^ bX[nf]) << 4));
#pragma unroll
            for (int mf = 0; mf < 4; mf++)
#pragma unroll
                for (int nf = 0; nf < 4; nf++)
                    mma16816(acc[mf][nf], a[mf], b[nf]);
        }

        cur = (cur == 2) ? 0 : cur + 1;
        pf  = (pf == 2) ? 0 : pf + 1;
    }

    int g = lane >> 2, tig = lane & 3;
    int which = bx / dstTiles;
    int lbx = bx - which * dstTiles;
    __half* D = (which == 0) ? D0 : ((which == 1) ? D1 : D2);
#pragma unroll
    for (int mf = 0; mf < 4; mf++) {
#pragma unroll
        for (int nf = 0; nf < 4; nf++) {
            int r0 = by * 128 + wm * 64 + mf * 16 + g;
            int cl = wn * 32 + nf * 8 + tig * 2;
            int cglob = bx * 128 + cl;
            float b0 = 0.f, b1 = 0.f;
            if (bias) { b0 = bias[cglob]; b1 = bias[cglob + 1]; }
            float v0 = acc[mf][nf][0] + b0, v1 = acc[mf][nf][1] + b1;
            float v2 = acc[mf][nf][2] + b0, v3 = acc[mf][nf][3] + b1;
            if (relu) {
                v0 = fmaxf(v0, 0.f); v1 = fmaxf(v1, 0.f);
                v2 = fmaxf(v2, 0.f); v3 = fmaxf(v3, 0.f);
            }
            if (C32) {
                *(float2*)(C32 + (size_t)r0 * N + cglob) = make_float2(v0, v1);
                *(float2*)(C32 + (size_t)(r0 + 8) * N + cglob) = make_float2(v2, v3);
            } else {
                int c = lbx * 128 + cl;
                *(__half2*)(D + (size_t)r0 * outLd + c) = __floats2half2_rn(v0, v1);
                *(__half2*)(D + (size_t)(r0 + 8) * outLd + c) = __floats2half2_rn(v2, v3);
            }
        }
    }
}

// ---------------------------------------------------------------------------
// Tensor-core flash attention (R7 version — known good).
// grid (BATCH*NH, T/64), 128 threads. log2-domain softmax.
// ---------------------------------------------------------------------------
__global__ void __launch_bounds__(128)
fa_mma_kernel(const __half* __restrict__ Qm, const __half* __restrict__ Km,
              const __half* __restrict__ Vm, __half* __restrict__ Oh, int causal)
{
    __shared__ __half sQ[64 * 64];
    __shared__ __half sK[2][64 * 64];
    __shared__ __half sV[2][64 * 64];

    int tid = threadIdx.x, lane = tid & 31, w = tid >> 5;
    int g = lane >> 2, tig = lane & 3;
    int bh = blockIdx.x, b = bh >> 4, h = bh & 15;
    int qt = blockIdx.y;

    uint32_t sq = smem_u32(sQ);
    uint32_t skb[2] = { smem_u32(sK[0]), smem_u32(sK[1]) };
    uint32_t svb[2] = { smem_u32(sV[0]), smem_u32(sV[1]) };

    const __half* Qg = Qm + ((size_t)(b * T + qt * 64)) * E + h * HS;
    const __half* K0 = Km + ((size_t)(b * T)) * E + h * HS;
    const __half* V0 = Vm + ((size_t)(b * T)) * E + h * HS;

#pragma unroll
    for (int i = 0; i < 4; i++) {
        int c = tid + i * 128; int r = c >> 3; int ch = c & 7;
        uint32_t off = r * 128 + ((ch ^ (r & 7)) << 4);
        CP_ASYNC16(sq + off, Qg + (size_t)r * E + ch * 8);
        CP_ASYNC16(skb[0] + off, K0 + (size_t)r * E + ch * 8);
        CP_ASYNC16(svb[0] + off, V0 + (size_t)r * E + ch * 8);
    }
    CP_COMMIT();
    CP_WAIT0();
    __syncthreads();

    uint32_t qf[4][4];
    {
        int r = w * 16 + (lane & 15); int sel = lane >> 4; int rx = r & 7;
        uint32_t ro = sq + r * 128;
#pragma unroll
        for (int ks = 0; ks < 4; ks++)
            LDSM4(qf[ks], ro + (((2 * ks + sel) ^ rx) << 4));
    }

    float oacc[8][4];
#pragma unroll
    for (int n = 0; n < 8; n++)
#pragma unroll
        for (int e = 0; e < 4; e++) oacc[n][e] = 0.f;
    float m0 = -1e30f, m1 = -1e30f, l0 = 0.f, l1 = 0.f;

    int nk = causal ? (qt + 1) : (T / 64);
    const float SC2 = ATT_SCALE * LOG2E;   // scores in log2 domain

    for (int kt = 0; kt < nk; kt++) {
        int cur = kt & 1;
        if (kt + 1 < nk) {
            int nst = cur ^ 1;
            const __half* Kg = Km + ((size_t)(b * T + (kt + 1) * 64)) * E + h * HS;
            const __half* Vg = Vm + ((size_t)(b * T + (kt + 1) * 64)) * E + h * HS;
#pragma unroll
            for (int i = 0; i < 4; i++) {
                int c = tid + i * 128; int r = c >> 3; int ch = c & 7;
                uint32_t off = r * 128 + ((ch ^ (r & 7)) << 4);
                CP_ASYNC16(skb[nst] + off, Kg + (size_t)r * E + ch * 8);
                CP_ASYNC16(svb[nst] + off, Vg + (size_t)r * E + ch * 8);
            }
            CP_COMMIT();
        }

        float sacc[8][4];
#pragma unroll
        for (int n = 0; n < 8; n++)
#pragma unroll
            for (int e = 0; e < 4; e++) sacc[n][e] = 0.f;

        uint32_t skc = skb[cur], svc = svb[cur];
#pragma unroll
        for (int ks = 0; ks < 4; ks++) {
            uint32_t kb[8][2];
            int rl = lane & 7, sel = (lane >> 3) & 1;
#pragma unroll
            for (int n = 0; n < 8; n++) {
                int rr = n * 8 + rl;
                LDSM2(kb[n], skc + rr * 128 + (((2 * ks + sel) ^ (rr & 7)) << 4));
            }
#pragma unroll
            for (int n = 0; n < 8; n++) mma16816(sacc[n], qf[ks], kb[n]);
        }

#pragma unroll
        for (int n = 0; n < 8; n++)
#pragma unroll
            for (int e = 0; e < 4; e++) sacc[n][e] *= SC2;
        if (causal && kt == qt) {
            int row0 = w * 16 + g;
#pragma unroll
            for (int n = 0; n < 8; n++) {
                int c0 = n * 8 + tig * 2;
                if (c0     > row0)     sacc[n][0] = -1e30f;
                if (c0 + 1 > row0)     sacc[n][1] = -1e30f;
                if (c0     > row0 + 8) sacc[n][2] = -1e30f;
                if (c0 + 1 > row0 + 8) sacc[n][3] = -1e30f;
            }
        }

        float mx0 = -1e30f, mx1 = -1e30f;
#pragma unroll
        for (int n = 0; n < 8; n++) {
            mx0 = fmaxf(mx0, fmaxf(sacc[n][0], sacc[n][1]));
            mx1 = fmaxf(mx1, fmaxf(sacc[n][2], sacc[n][3]));
        }
        mx0 = fmaxf(mx0, __shfl_xor_sync(0xffffffffu, mx0, 1));
        mx0 = fmaxf(mx0, __shfl_xor_sync(0xffffffffu, mx0, 2));
        mx1 = fmaxf(mx1, __shfl_xor_sync(0xffffffffu, mx1, 1));
        mx1 = fmaxf(mx1, __shfl_xor_sync(0xffffffffu, mx1, 2));
        float mn0 = fmaxf(m0, mx0), mn1 = fmaxf(m1, mx1);
        float a0 = exp2f(m0 - mn0), a1 = exp2f(m1 - mn1);
        m0 = mn0; m1 = mn1;

        float ps0 = 0.f, ps1 = 0.f;
        uint32_t pfr[4][4];
#pragma unroll
        for (int n = 0; n < 8; n++) {
            float p0 = exp2f(sacc[n][0] - mn0), p1 = exp2f(sacc[n][1] - mn0);
            float p2 = exp2f(sacc[n][2] - mn1), p3 = exp2f(sacc[n][3] - mn1);
            ps0 += p0 + p1; ps1 += p2 + p3;
            __half2 h01 = __floats2half2_rn(p0, p1);
            __half2 h23 = __floats2half2_rn(p2, p3);
            int ks = n >> 1, hi = (n & 1) * 2;
            pfr[ks][hi]     = *(uint32_t*)&h01;
            pfr[ks][hi + 1] = *(uint32_t*)&h23;
        }
        l0 = l0 * a0 + ps0;
        l1 = l1 * a1 + ps1;
#pragma unroll
        for (int n = 0; n < 8; n++) {
            oacc[n][0] *= a0; oacc[n][1] *= a0;
            oacc[n][2] *= a1; oacc[n][3] *= a1;
        }

        {
            int rl = lane & 15, cs = lane >> 4;
#pragma unroll
            for (int np = 0; np < 4; np++) {
#pragma unroll
                for (int ks = 0; ks < 4; ks++) {
                    uint32_t vb[4];
                    int rr = ks * 16 + rl;
                    int ch = np * 2 + cs;
                    LDSM4T(vb, svc + rr * 128 + ((ch ^ (rr & 7)) << 4));
                    mma16816(oacc[2 * np],     pfr[ks], vb);
                    mma16816(oacc[2 * np + 1], pfr[ks], vb + 2);
                }
            }
        }

        CP_WAIT0();
        __syncthreads();
    }

    l0 += __shfl_xor_sync(0xffffffffu, l0, 1);
    l0 += __shfl_xor_sync(0xffffffffu, l0, 2);
    l1 += __shfl_xor_sync(0xffffffffu, l1, 1);
    l1 += __shfl_xor_sync(0xffffffffu, l1, 2);
    float i0 = 1.f / l0, i1 = 1.f / l1;

    size_t base0 = ((size_t)(b * T + qt * 64 + w * 16 + g)) * E + h * HS;
    size_t base1 = base0 + (size_t)8 * E;
#pragma unroll
    for (int n = 0; n < 8; n++) {
        int c = n * 8 + tig * 2;
        *(__half2*)(Oh + base0 + c) = __floats2half2_rn(oacc[n][0] * i0, oacc[n][1] * i0);
        *(__half2*)(Oh + base1 + c) = __floats2half2_rn(oacc[n][2] * i1, oacc[n][3] * i1);
    }
}

// ---------------------------------------------------------------------------
// Batched weight transpose to fp16 (8 equal E x E matrices, one launch)
// ---------------------------------------------------------------------------
struct TP8 { const float* s[8]; __half* d[8]; };

__global__ void __launch_bounds__(256)
transpose8_kernel(TP8 p)
{
    __shared__ float t[32][33];
    const float* in = p.s[blockIdx.z];
    __half* out = p.d[blockIdx.z];
    int bx = blockIdx.x * 32, by = blockIdx.y * 32;
    int x = threadIdx.x, y = threadIdx.y;
#pragma unroll
    for (int j = 0; j < 32; j += 8)
        t[y + j][x] = in[(size_t)(by + y + j) * E + bx + x];
    __syncthreads();
#pragma unroll
    for (int j = 0; j < 32; j += 8)
        out[(size_t)(bx + y + j) * E + by + x] = __float2half(t[x][y + j]);
}

// Batched transpose for the two FFN weights.
__global__ void __launch_bounds__(256)
transpose_ff_kernel(const float* __restrict__ w1, __half* __restrict__ w1t,
                    const float* __restrict__ w2, __half* __restrict__ w2t)
{
    __shared__ float t[32][33];
    const float* in;  __half* out;  int R, C;
    if (blockIdx.z == 0) { in = w1; out = w1t; R = E;  C = HID; }
    else                 { in = w2; out = w2t; R = HID; C = E;  }
    int bx = blockIdx.x * 32, by = blockIdx.y * 32;
    if (bx >= C || by >= R) return;
    int x = threadIdx.x, y = threadIdx.y;
#pragma unroll
    for (int j = 0; j < 32; j += 8)
        t[y + j][x] = in[(size_t)(by + y + j) * C + bx + x];
    __syncthreads();
#pragma unroll
    for (int j = 0; j < 32; j += 8)
        out[(size_t)(bx + y + j) * R + by + x] = __float2half(t[x][y + j]);
}

// ---------------------------------------------------------------------------
// Dual fp32 -> fp16 convert (x and context), 4 float4s per thread
// ---------------------------------------------------------------------------
__global__ void __launch_bounds__(256)
conv2_h_kernel(const float* __restrict__ a, __half* __restrict__ ah,
               const float* __restrict__ b, __half* __restrict__ bh, int n)
{
    const float* src = blockIdx.y ? b : a;
    __half* dst = blockIdx.y ? bh : ah;
    int base = (blockIdx.x * 256 + threadIdx.x) * 4;
    int stride = gridDim.x * 256 * 4;
#pragma unroll
    for (int k = 0; k < 4; k++) {
        int i = base + k * stride;
        if (i < n) {
            float4 v = *(const float4*)(src + i);
            *(__half2*)(dst + i)     = __floats2half2_rn(v.x, v.y);
            *(__half2*)(dst + i + 2) = __floats2half2_rn(v.z, v.w);
        }
    }
}

// ---------------------------------------------------------------------------
// Fused residual + LayerNorm, fp16 residual input (+ optional fp16 plane)
// out = LN(x + r) * g + b.  X fp32, R fp16. float4/half2 I/O.
// ---------------------------------------------------------------------------
__global__ void __launch_bounds__(256)
ln_residual_kernel(const float* __restrict__ X, const __half* __restrict__ R,
                   const float* __restrict__ G, const float* __restrict__ Bt,
                   float* __restrict__ Out, __half* __restrict__ Oh)
{
    const int N = E;
    int row = blockIdx.x;
    int tid = threadIdx.x;
    int lane = tid & 31, wid = tid >> 5;
    __shared__ float sm[8];
    __shared__ float stats[2];

    int idx = tid * 4;
    float4 xv = *(const float4*)(X + (size_t)row * N + idx);
    __half2 r01 = *(const __half2*)(R + (size_t)row * N + idx);
    __half2 r23 = *(const __half2*)(R + (size_t)row * N + idx + 2);
    float2 rf01 = __half22float2(r01);
    float2 rf23 = __half22float2(r23);
    float v0 = xv.x + rf01.x, v1 = xv.y + rf01.y;
    float v2 = xv.z + rf23.x, v3 = xv.w + rf23.y;

    float s = (v0 + v1) + (v2 + v3);
#pragma unroll
    for (int off = 16; off > 0; off >>= 1) s += __shfl_down_sync(0xffffffffu, s, off);
    if (lane == 0) sm[wid] = s;
    __syncthreads();
    if (tid == 0) {
        float t = 0.f;
#pragma unroll
        for (int i = 0; i < 8; i++) t += sm[i];
        stats[0] = t * (1.f / N);
    }
    __syncthreads();
    float mu = stats[0];

    float d0 = v0 - mu, d1 = v1 - mu, d2 = v2 - mu, d3 = v3 - mu;
    float vs = (d0 * d0 + d1 * d1) + (d2 * d2 + d3 * d3);
#pragma unroll
    for (int off = 16; off > 0; off >>= 1) vs += __shfl_down_sync(0xffffffffu, vs, off);
    __syncthreads();
    if (lane == 0) sm[wid] = vs;
    __syncthreads();
    if (tid == 0) {
        float t = 0.f;
#pragma unroll
        for (int i = 0; i < 8; i++) t += sm[i];
        stats[1] = rsqrtf(t * (1.f / N) + LN_EPS);
    }
    __syncthreads();
    float rstd = stats[1];

    float4 gv = *(const float4*)(G + idx);
    float4 bv = *(const float4*)(Bt + idx);
    float y0 = d0 * rstd * gv.x + bv.x;
    float y1 = d1 * rstd * gv.y + bv.y;
    float y2 = d2 * rstd * gv.z + bv.z;
    float y3 = d3 * rstd * gv.w + bv.w;
    *(float4*)(Out + (size_t)row * N + idx) = make_float4(y0, y1, y2, y3);
    if (Oh) {
        *(__half2*)(Oh + (size_t)row * N + idx)     = __floats2half2_rn(y0, y1);
        *(__half2*)(Oh + (size_t)row * N + idx + 2) = __floats2half2_rn(y2, y3);
    }
}

// ---------------------------------------------------------------------------
// Launch
// ---------------------------------------------------------------------------
extern "C" void kernel_launch(void* const* d_in, const int* in_sizes, int n_in,
                              void* d_out, int out_size)
{
    const float* x       = (const float*)d_in[0];
    const float* context = (const float*)d_in[1];
    const float* sa_wq = (const float*)d_in[2];
    const float* sa_wk = (const float*)d_in[3];
    const float* sa_wv = (const float*)d_in[4];
    const float* sa_wo = (const float*)d_in[5];
    const float* sa_bo = (const float*)d_in[6];
    const float* ca_wq = (const float*)d_in[7];
    const float* ca_wk = (const float*)d_in[8];
    const float* ca_wv = (const float*)d_in[9];
    const float* ca_wo = (const float*)d_in[10];
    const float* ca_bo = (const float*)d_in[11];
    const float* n1_g  = (const float*)d_in[12];
    const float* n1_b  = (const float*)d_in[13];
    const float* n2_g  = (const float*)d_in[14];
    const float* n2_b  = (const float*)d_in[15];
    const float* n3_g  = (const float*)d_in[16];
    const float* n3_b  = (const float*)d_in[17];
    const float* ff_w1 = (const float*)d_in[18];
    const float* ff_b1 = (const float*)d_in[19];
    const float* ff_w2 = (const float*)d_in[20];
    const float* ff_b2 = (const float*)d_in[21];
    float* out = (float*)d_out;

    float *x1f_, *x2f_;
    cudaGetSymbolAddress((void**)&x1f_, g_x1f);
    cudaGetSymbolAddress((void**)&x2f_, g_x2f);

    __half *tmph, *qh, *kh, *vh, *ath;
    cudaGetSymbolAddress((void**)&tmph, g_tmph);
    cudaGetSymbolAddress((void**)&qh,  g_qh);
    cudaGetSymbolAddress((void**)&kh,  g_kh);
    cudaGetSymbolAddress((void**)&vh,  g_vh);
    cudaGetSymbolAddress((void**)&ath, g_ath);

    __half *xh, *ctxh, *x1h, *x2h, *ffh;
    cudaGetSymbolAddress((void**)&xh,   g_xh);
    cudaGetSymbolAddress((void**)&ctxh, g_ctxh);
    cudaGetSymbolAddress((void**)&x1h,  g_x1h);
    cudaGetSymbolAddress((void**)&x2h,  g_x2h);
    cudaGetSymbolAddress((void**)&ffh,  g_ffh);

    __half *wqkv, *wqkvca, *wot, *cwot, *w1t, *w2t;
    cudaGetSymbolAddress((void**)&wqkv,   g_wqkv_sa);
    cudaGetSymbolAddress((void**)&wqkvca, g_wqkv_ca);
    cudaGetSymbolAddress((void**)&wot,    g_sa_wot);
    cudaGetSymbolAddress((void**)&cwot,   g_ca_wot);
    cudaGetSymbolAddress((void**)&w1t,    g_w1t);
    cudaGetSymbolAddress((void**)&w2t,    g_w2t);

    cudaFuncSetAttribute(hgemm1_kernel,
                         cudaFuncAttributeMaxDynamicSharedMemorySize, HG1_SMEM);

    // 8 E x E transposes in one launch
    TP8 tp;
    tp.s[0] = sa_wq; tp.d[0] = wqkv;
    tp.s[1] = sa_wk; tp.d[1] = wqkv + E * E;
    tp.s[2] = sa_wv; tp.d[2] = wqkv + 2 * E * E;
    tp.s[3] = sa_wo; tp.d[3] = wot;
    tp.s[4] = ca_wq; tp.d[4] = wqkvca;
    tp.s[5] = ca_wk; tp.d[5] = wqkvca + E * E;
    tp.s[6] = ca_wv; tp.d[6] = wqkvca + 2 * E * E;
    tp.s[7] = ca_wo; tp.d[7] = cwot;
    dim3 tB(32, 8);
    transpose8_kernel<<<dim3(E / 32, E / 32, 8), tB>>>(tp);
    transpose_ff_kernel<<<dim3(HID / 32, HID / 32, 2), tB>>>(ff_w1, w1t, ff_w2, w2t);

    int nElem = M_ROWS * E;
    conv2_h_kernel<<<dim3(nElem / 4096, 2), 256>>>(x, xh, context, ctxh, nElem);

    dim3 gQKV(3 * E / 128, M_ROWS / 128);   // 24 x 32
    dim3 gE(E / 128, M_ROWS / 128);         // 8 x 32
    dim3 gH(HID / 128, M_ROWS / 128);       // 32 x 32
    dim3 gFA(BATCH * NH, T / 64);

    // ---- Self-attention ----
    hgemm1_kernel<<<gQKV, 256, HG1_SMEM>>>(xh, nullptr, 1 << 30, wqkv, nullptr, nullptr,
                                           qh, kh, vh, 8, E, 3 * E, E, 0);
    fa_mma_kernel<<<gFA, 128>>>(qh, kh, vh, ath, 1);
    hgemm1_kernel<<<gE, 256, HG1_SMEM>>>(ath, nullptr, 1 << 30, wot, sa_bo, nullptr,
                                         tmph, nullptr, nullptr, 8, E, E, E, 0);
    ln_residual_kernel<<<M_ROWS, 256>>>(x, tmph, n1_g, n1_b, x1f_, x1h);

    // ---- Cross-attention (q from x1h, k/v from ctxh; one launch) ----
    hgemm1_kernel<<<gQKV, 256, HG1_SMEM>>>(x1h, ctxh, 8, wqkvca, nullptr, nullptr,
                                           qh, kh, vh, 8, E, 3 * E, E, 0);
    fa_mma_kernel<<<gFA, 128>>>(qh, kh, vh, ath, 0);
    hgemm1_kernel<<<gE, 256, HG1_SMEM>>>(ath, nullptr, 1 << 30, cwot, ca_bo, nullptr,
                                         tmph, nullptr, nullptr, 8, E, E, E, 0);
    ln_residual_kernel<<<M_ROWS, 256>>>(x1f_, tmph, n2_g, n2_b, x2f_, x2h);

    // ---- FFN ----
    hgemm1_kernel<<<gH, 256, HG1_SMEM>>>(x2h, nullptr, 1 << 30, w1t, ff_b1, nullptr,
                                         ffh, nullptr, nullptr, 32, HID, HID, E, 1);
    hgemm1_kernel<<<gE, 256, HG1_SMEM>>>(ffh, nullptr, 1 << 30, w2t, ff_b2, nullptr,
                                         tmph, nullptr, nullptr, 8, E, E, HID, 0);
    ln_residual_kernel<<<M_ROWS, 256>>>(x2f_, tmph, n3_g, n3_b, out, nullptr);
}

// round 13
// speedup vs baseline: 1.0278x; 1.0106x over previous
#include <cuda_runtime.h>
#include <cuda_fp16.h>
#include <math.h>
#include <stdint.h>

// Problem constants
#define BATCH 4
#define T 1024
#define E 1024
#define NH 16
#define HS 64
#define HID 4096
#define M_ROWS (BATCH * T)   // 4096
#define LN_EPS 1e-5f
#define ATT_SCALE 0.03125f   // E^-0.25 on q and k each -> E^-0.5 on dot
#define LOG2E 1.4426950408889634f

// ---------------------------------------------------------------------------
// Scratch (__device__ globals; no allocation allowed)
// ---------------------------------------------------------------------------
__device__ float  g_x1f[M_ROWS * E];
__device__ float  g_x2f[M_ROWS * E];
__device__ __half g_tmph[M_ROWS * E];
__device__ __half g_qh[M_ROWS * E], g_kh[M_ROWS * E], g_vh[M_ROWS * E];
__device__ __half g_ath[M_ROWS * E];
__device__ __half g_xh[M_ROWS * E];
__device__ __half g_ctxh[M_ROWS * E];
__device__ __half g_x1h[M_ROWS * E];
__device__ __half g_x2h[M_ROWS * E];
__device__ __half g_ffh[M_ROWS * HID];
// fp16 transposed weights [N,K] (QKV packed for fused projections)
__device__ __half g_wqkv_sa[3 * E * E];         // wq^T | wk^T | wv^T
__device__ __half g_wqkv_ca[3 * E * E];         // wq^T | wk^T | wv^T
__device__ __half g_sa_wot[E * E], g_ca_wot[E * E];
__device__ __half g_w1t[HID * E], g_w2t[E * HID];

// ---------------------------------------------------------------------------
// PTX helpers (sm_80+-compatible: cp.async, ldmatrix, mma.sync)
// ---------------------------------------------------------------------------
__device__ __forceinline__ uint32_t smem_u32(const void* p) {
    uint32_t a;
    asm("{ .reg .u64 t; cvta.to.shared.u64 t, %1; cvt.u32.u64 %0, t; }"
        : "=r"(a) : "l"(p));
    return a;
}

#define CP_ASYNC16(saddr, gptr) \
    asm volatile("cp.async.cg.shared.global [%0], [%1], 16;" \
        :: "r"(saddr), "l"(gptr) : "memory")
#define CP_COMMIT()  asm volatile("cp.async.commit_group;" ::: "memory")
#define CP_WAIT0()   asm volatile("cp.async.wait_group 0;" ::: "memory")
#define CP_WAIT1()   asm volatile("cp.async.wait_group 1;" ::: "memory")

#define LDSM4(r, addr) \
    asm volatile("ldmatrix.sync.aligned.m8n8.x4.shared.b16 {%0,%1,%2,%3}, [%4];" \
        : "=r"((r)[0]), "=r"((r)[1]), "=r"((r)[2]), "=r"((r)[3]) : "r"(addr))
#define LDSM2(r, addr) \
    asm volatile("ldmatrix.sync.aligned.m8n8.x2.shared.b16 {%0,%1}, [%2];" \
        : "=r"((r)[0]), "=r"((r)[1]) : "r"(addr))
#define LDSM4T(r, addr) \
    asm volatile("ldmatrix.sync.aligned.m8n8.x4.trans.shared.b16 {%0,%1,%2,%3}, [%4];" \
        : "=r"((r)[0]), "=r"((r)[1]), "=r"((r)[2]), "=r"((r)[3]) : "r"(addr))

__device__ __forceinline__ void mma16816(float* c, const uint32_t* a, const uint32_t* b) {
    asm volatile(
        "mma.sync.aligned.m16n8k16.row.col.f32.f16.f16.f32 "
        "{%0,%1,%2,%3}, {%4,%5,%6,%7}, {%8,%9}, {%0,%1,%2,%3};"
        : "+f"(c[0]), "+f"(c[1]), "+f"(c[2]), "+f"(c[3])
        : "r"(a[0]), "r"(a[1]), "r"(a[2]), "r"(a[3]), "r"(b[0]), "r"(b[1]));
}

// ===========================================================================
// Single-plane HGEMM (R7 version — known good): C = A[M,K] @ Bt[N,K]^T
// (+bias)(+relu). A selected per N-tile: bx < a2Start -> Ah, else A2.
// Output: fp32 C32 OR fp16 into up to 3 dest buffers (bx/dstTiles, ld outLd).
// Tile 128x128x64, 256 threads, 3-stage cp.async (96KB smem, 2 CTA/SM),
// single __syncthreads per ktile.
// ===========================================================================
#define HG1_STAGE 32768
#define HG1_SMEM  (3 * HG1_STAGE)

__global__ void __launch_bounds__(256, 2)
hgemm1_kernel(const __half* __restrict__ Ah, const __half* __restrict__ A2,
              int a2Start,
              const __half* __restrict__ Bt, const float* __restrict__ bias,
              float* __restrict__ C32,
              __half* __restrict__ D0, __half* __restrict__ D1, __half* __restrict__ D2,
              int dstTiles, int outLd, int N, int K, int relu)
{
    extern __shared__ char smem[];
    uint32_t sb = smem_u32(smem);
    int tid = threadIdx.x;
    int lane = tid & 31;
    int wid = tid >> 5;
    int wm = wid & 1, wn = wid >> 1;
    int bx = blockIdx.x, by = blockIdx.y;

    const __half* Abase = (bx < a2Start) ? Ah : A2;
    const __half* gA = Abase + (size_t)by * 128 * K;
    const __half* gB = Bt + (size_t)bx * 128 * K;

    int lrow = tid >> 3;
    int lch = tid & 7;
    uint32_t soff[4];
#pragma unroll
    for (int i = 0; i < 4; i++) {
        int r = lrow + 32 * i;
        soff[i] = (uint32_t)(r * 128 + ((lch ^ (r & 7)) * 16));
    }

    uint32_t aOff[4], aX[4], bOff[4], bX[4];
#pragma unroll
    for (int mf = 0; mf < 4; mf++) {
        int r = wm * 64 + mf * 16 + (lane & 15);
        aOff[mf] = r * 128; aX[mf] = r & 7;
    }
#pragma unroll
    for (int nf = 0; nf < 4; nf++) {
        int r = wn * 32 + nf * 8 + (lane & 7);
        bOff[nf] = r * 128; bX[nf] = r & 7;
    }
    int aSel = lane >> 4;
    int bSel = (lane >> 3) & 1;

    float acc[4][4][4];
#pragma unroll
    for (int mf = 0; mf < 4; mf++)
#pragma unroll
        for (int nf = 0; nf < 4; nf++)
#pragma unroll
            for (int r = 0; r < 4; r++) acc[mf][nf][r] = 0.f;

    const int KT = K >> 6;

    // Prologue: stage ktiles 0 and 1 into buffers 0 and 1
#pragma unroll
    for (int p = 0; p < 2; p++) {
        uint32_t st = sb + p * HG1_STAGE;
        int k0 = p << 6;
#pragma unroll
        for (int i = 0; i < 4; i++) {
            int r = lrow + 32 * i;
            CP_ASYNC16(st + soff[i],         gA + (size_t)r * K + k0 + lch * 8);
            CP_ASYNC16(st + 16384 + soff[i], gB + (size_t)r * K + k0 + lch * 8);
        }
        CP_COMMIT();
    }

    int cur = 0;   // buffer for current ktile
    int pf = 2;    // buffer for ktile kt+2
    for (int kt = 0; kt < KT; kt++) {
        if (kt + 2 < KT) { CP_WAIT1(); } else { CP_WAIT0(); }
        __syncthreads();

        if (kt + 2 < KT) {
            uint32_t st = sb + pf * HG1_STAGE;
            int k0 = (kt + 2) << 6;
#pragma unroll
            for (int i = 0; i < 4; i++) {
                int r = lrow + 32 * i;
                CP_ASYNC16(st + soff[i],         gA + (size_t)r * K + k0 + lch * 8);
                CP_ASYNC16(st + 16384 + soff[i], gB + (size_t)r * K + k0 + lch * 8);
            }
            CP_COMMIT();
        }

        uint32_t aBase = sb + cur * HG1_STAGE;
        uint32_t bBase = aBase + 16384;

#pragma unroll
        for (int ks = 0; ks < 4; ks++) {
            int cA = ks * 2 + aSel;
            int cB = ks * 2 + bSel;
            uint32_t a[4][4], b[4][2];
#pragma unroll
            for (int mf = 0; mf < 4; mf++)
                LDSM4(a[mf], aBase + aOff[mf] + ((cA ^ aX[mf]) << 4));
#pragma unroll
            for (int nf = 0; nf < 4; nf++)
                LDSM2(b[nf], bBase + bOff[nf] + ((cB ^ bX[nf]) << 4));
#pragma unroll
            for (int mf = 0; mf < 4; mf++)
#pragma unroll
                for (int nf = 0; nf < 4; nf++)
                    mma16816(acc[mf][nf], a[mf], b[nf]);
        }

        cur = (cur == 2) ? 0 : cur + 1;
        pf  = (pf == 2) ? 0 : pf + 1;
    }

    int g = lane >> 2, tig = lane & 3;
    int which = bx / dstTiles;
    int lbx = bx - which * dstTiles;
    __half* D = (which == 0) ? D0 : ((which == 1) ? D1 : D2);
#pragma unroll
    for (int mf = 0; mf < 4; mf++) {
#pragma unroll
        for (int nf = 0; nf < 4; nf++) {
            int r0 = by * 128 + wm * 64 + mf * 16 + g;
            int cl = wn * 32 + nf * 8 + tig * 2;
            int cglob = bx * 128 + cl;
            float b0 = 0.f, b1 = 0.f;
            if (bias) { b0 = bias[cglob]; b1 = bias[cglob + 1]; }
            float v0 = acc[mf][nf][0] + b0, v1 = acc[mf][nf][1] + b1;
            float v2 = acc[mf][nf][2] + b0, v3 = acc[mf][nf][3] + b1;
            if (relu) {
                v0 = fmaxf(v0, 0.f); v1 = fmaxf(v1, 0.f);
                v2 = fmaxf(v2, 0.f); v3 = fmaxf(v3, 0.f);
            }
            if (C32) {
                *(float2*)(C32 + (size_t)r0 * N + cglob) = make_float2(v0, v1);
                *(float2*)(C32 + (size_t)(r0 + 8) * N + cglob) = make_float2(v2, v3);
            } else {
                int c = lbx * 128 + cl;
                *(__half2*)(D + (size_t)r0 * outLd + c) = __floats2half2_rn(v0, v1);
                *(__half2*)(D + (size_t)(r0 + 8) * outLd + c) = __floats2half2_rn(v2, v3);
            }
        }
    }
}

// ---------------------------------------------------------------------------
// Tensor-core flash attention (R7 version — known good).
// grid (BATCH*NH, T/64), 128 threads. log2-domain softmax.
// ---------------------------------------------------------------------------
__global__ void __launch_bounds__(128)
fa_mma_kernel(const __half* __restrict__ Qm, const __half* __restrict__ Km,
              const __half* __restrict__ Vm, __half* __restrict__ Oh, int causal)
{
    __shared__ __half sQ[64 * 64];
    __shared__ __half sK[2][64 * 64];
    __shared__ __half sV[2][64 * 64];

    int tid = threadIdx.x, lane = tid & 31, w = tid >> 5;
    int g = lane >> 2, tig = lane & 3;
    int bh = blockIdx.x, b = bh >> 4, h = bh & 15;
    int qt = blockIdx.y;

    uint32_t sq = smem_u32(sQ);
    uint32_t skb[2] = { smem_u32(sK[0]), smem_u32(sK[1]) };
    uint32_t svb[2] = { smem_u32(sV[0]), smem_u32(sV[1]) };

    const __half* Qg = Qm + ((size_t)(b * T + qt * 64)) * E + h * HS;
    const __half* K0 = Km + ((size_t)(b * T)) * E + h * HS;
    const __half* V0 = Vm + ((size_t)(b * T)) * E + h * HS;

#pragma unroll
    for (int i = 0; i < 4; i++) {
        int c = tid + i * 128; int r = c >> 3; int ch = c & 7;
        uint32_t off = r * 128 + ((ch ^ (r & 7)) << 4);
        CP_ASYNC16(sq + off, Qg + (size_t)r * E + ch * 8);
        CP_ASYNC16(skb[0] + off, K0 + (size_t)r * E + ch * 8);
        CP_ASYNC16(svb[0] + off, V0 + (size_t)r * E + ch * 8);
    }
    CP_COMMIT();
    CP_WAIT0();
    __syncthreads();

    uint32_t qf[4][4];
    {
        int r = w * 16 + (lane & 15); int sel = lane >> 4; int rx = r & 7;
        uint32_t ro = sq + r * 128;
#pragma unroll
        for (int ks = 0; ks < 4; ks++)
            LDSM4(qf[ks], ro + (((2 * ks + sel) ^ rx) << 4));
    }

    float oacc[8][4];
#pragma unroll
    for (int n = 0; n < 8; n++)
#pragma unroll
        for (int e = 0; e < 4; e++) oacc[n][e] = 0.f;
    float m0 = -1e30f, m1 = -1e30f, l0 = 0.f, l1 = 0.f;

    int nk = causal ? (qt + 1) : (T / 64);
    const float SC2 = ATT_SCALE * LOG2E;   // scores in log2 domain

    for (int kt = 0; kt < nk; kt++) {
        int cur = kt & 1;
        if (kt + 1 < nk) {
            int nst = cur ^ 1;
            const __half* Kg = Km + ((size_t)(b * T + (kt + 1) * 64)) * E + h * HS;
            const __half* Vg = Vm + ((size_t)(b * T + (kt + 1) * 64)) * E + h * HS;
#pragma unroll
            for (int i = 0; i < 4; i++) {
                int c = tid + i * 128; int r = c >> 3; int ch = c & 7;
                uint32_t off = r * 128 + ((ch ^ (r & 7)) << 4);
                CP_ASYNC16(skb[nst] + off, Kg + (size_t)r * E + ch * 8);
                CP_ASYNC16(svb[nst] + off, Vg + (size_t)r * E + ch * 8);
            }
            CP_COMMIT();
        }

        float sacc[8][4];
#pragma unroll
        for (int n = 0; n < 8; n++)
#pragma unroll
            for (int e = 0; e < 4; e++) sacc[n][e] = 0.f;

        uint32_t skc = skb[cur], svc = svb[cur];
#pragma unroll
        for (int ks = 0; ks < 4; ks++) {
            uint32_t kb[8][2];
            int rl = lane & 7, sel = (lane >> 3) & 1;
#pragma unroll
            for (int n = 0; n < 8; n++) {
                int rr = n * 8 + rl;
                LDSM2(kb[n], skc + rr * 128 + (((2 * ks + sel) ^ (rr & 7)) << 4));
            }
#pragma unroll
            for (int n = 0; n < 8; n++) mma16816(sacc[n], qf[ks], kb[n]);
        }

#pragma unroll
        for (int n = 0; n < 8; n++)
#pragma unroll
            for (int e = 0; e < 4; e++) sacc[n][e] *= SC2;
        if (causal && kt == qt) {
            int row0 = w * 16 + g;
#pragma unroll
            for (int n = 0; n < 8; n++) {
                int c0 = n * 8 + tig * 2;
                if (c0     > row0)     sacc[n][0] = -1e30f;
                if (c0 + 1 > row0)     sacc[n][1] = -1e30f;
                if (c0     > row0 + 8) sacc[n][2] = -1e30f;
                if (c0 + 1 > row0 + 8) sacc[n][3] = -1e30f;
            }
        }

        float mx0 = -1e30f, mx1 = -1e30f;
#pragma unroll
        for (int n = 0; n < 8; n++) {
            mx0 = fmaxf(mx0, fmaxf(sacc[n][0], sacc[n][1]));
            mx1 = fmaxf(mx1, fmaxf(sacc[n][2], sacc[n][3]));
        }
        mx0 = fmaxf(mx0, __shfl_xor_sync(0xffffffffu, mx0, 1));
        mx0 = fmaxf(mx0, __shfl_xor_sync(0xffffffffu, mx0, 2));
        mx1 = fmaxf(mx1, __shfl_xor_sync(0xffffffffu, mx1, 1));
        mx1 = fmaxf(mx1, __shfl_xor_sync(0xffffffffu, mx1, 2));
        float mn0 = fmaxf(m0, mx0), mn1 = fmaxf(m1, mx1);
        float a0 = exp2f(m0 - mn0), a1 = exp2f(m1 - mn1);
        m0 = mn0; m1 = mn1;

        float ps0 = 0.f, ps1 = 0.f;
        uint32_t pfr[4][4];
#pragma unroll
        for (int n = 0; n < 8; n++) {
            float p0 = exp2f(sacc[n][0] - mn0), p1 = exp2f(sacc[n][1] - mn0);
            float p2 = exp2f(sacc[n][2] - mn1), p3 = exp2f(sacc[n][3] - mn1);
            ps0 += p0 + p1; ps1 += p2 + p3;
            __half2 h01 = __floats2half2_rn(p0, p1);
            __half2 h23 = __floats2half2_rn(p2, p3);
            int ks = n >> 1, hi = (n & 1) * 2;
            pfr[ks][hi]     = *(uint32_t*)&h01;
            pfr[ks][hi + 1] = *(uint32_t*)&h23;
        }
        l0 = l0 * a0 + ps0;
        l1 = l1 * a1 + ps1;
#pragma unroll
        for (int n = 0; n < 8; n++) {
            oacc[n][0] *= a0; oacc[n][1] *= a0;
            oacc[n][2] *= a1; oacc[n][3] *= a1;
        }

        {
            int rl = lane & 15, cs = lane >> 4;
#pragma unroll
            for (int np = 0; np < 4; np++) {
#pragma unroll
                for (int ks = 0; ks < 4; ks++) {
                    uint32_t vb[4];
                    int rr = ks * 16 + rl;
                    int ch = np * 2 + cs;
                    LDSM4T(vb, svc + rr * 128 + ((ch ^ (rr & 7)) << 4));
                    mma16816(oacc[2 * np],     pfr[ks], vb);
                    mma16816(oacc[2 * np + 1], pfr[ks], vb + 2);
                }
            }
        }

        CP_WAIT0();
        __syncthreads();
    }

    l0 += __shfl_xor_sync(0xffffffffu, l0, 1);
    l0 += __shfl_xor_sync(0xffffffffu, l0, 2);
    l1 += __shfl_xor_sync(0xffffffffu, l1, 1);
    l1 += __shfl_xor_sync(0xffffffffu, l1, 2);
    float i0 = 1.f / l0, i1 = 1.f / l1;

    size_t base0 = ((size_t)(b * T + qt * 64 + w * 16 + g)) * E + h * HS;
    size_t base1 = base0 + (size_t)8 * E;
#pragma unroll
    for (int n = 0; n < 8; n++) {
        int c = n * 8 + tig * 2;
        *(__half2*)(Oh + base0 + c) = __floats2half2_rn(oacc[n][0] * i0, oacc[n][1] * i0);
        *(__half2*)(Oh + base1 + c) = __floats2half2_rn(oacc[n][2] * i1, oacc[n][3] * i1);
    }
}

// ---------------------------------------------------------------------------
// Batched weight transpose to fp16 (up to 8 E x E matrices; count = gridDim.z)
// ---------------------------------------------------------------------------
struct TP8 { const float* s[8]; __half* d[8]; };

__global__ void __launch_bounds__(256)
transpose8_kernel(TP8 p)
{
    __shared__ float t[32][33];
    const float* in = p.s[blockIdx.z];
    __half* out = p.d[blockIdx.z];
    int bx = blockIdx.x * 32, by = blockIdx.y * 32;
    int x = threadIdx.x, y = threadIdx.y;
#pragma unroll
    for (int j = 0; j < 32; j += 8)
        t[y + j][x] = in[(size_t)(by + y + j) * E + bx + x];
    __syncthreads();
#pragma unroll
    for (int j = 0; j < 32; j += 8)
        out[(size_t)(bx + y + j) * E + by + x] = __float2half(t[x][y + j]);
}

// Batched transpose for the two FFN weights.
__global__ void __launch_bounds__(256)
transpose_ff_kernel(const float* __restrict__ w1, __half* __restrict__ w1t,
                    const float* __restrict__ w2, __half* __restrict__ w2t)
{
    __shared__ float t[32][33];
    const float* in;  __half* out;  int R, C;
    if (blockIdx.z == 0) { in = w1; out = w1t; R = E;  C = HID; }
    else                 { in = w2; out = w2t; R = HID; C = E;  }
    int bx = blockIdx.x * 32, by = blockIdx.y * 32;
    if (bx >= C || by >= R) return;
    int x = threadIdx.x, y = threadIdx.y;
#pragma unroll
    for (int j = 0; j < 32; j += 8)
        t[y + j][x] = in[(size_t)(by + y + j) * C + bx + x];
    __syncthreads();
#pragma unroll
    for (int j = 0; j < 32; j += 8)
        out[(size_t)(bx + y + j) * R + by + x] = __float2half(t[x][y + j]);
}

// ---------------------------------------------------------------------------
// Single fp32 -> fp16 convert, 4 float4s per thread
// ---------------------------------------------------------------------------
__global__ void __launch_bounds__(256)
conv1_h_kernel(const float* __restrict__ src, __half* __restrict__ dst, int n)
{
    int base = (blockIdx.x * 256 + threadIdx.x) * 4;
    int stride = gridDim.x * 256 * 4;
#pragma unroll
    for (int k = 0; k < 4; k++) {
        int i = base + k * stride;
        if (i < n) {
            float4 v = *(const float4*)(src + i);
            *(__half2*)(dst + i)     = __floats2half2_rn(v.x, v.y);
            *(__half2*)(dst + i + 2) = __floats2half2_rn(v.z, v.w);
        }
    }
}

// ---------------------------------------------------------------------------
// Fused residual + LayerNorm, fp16 residual input (+ optional fp16 plane)
// ---------------------------------------------------------------------------
__global__ void __launch_bounds__(256)
ln_residual_kernel(const float* __restrict__ X, const __half* __restrict__ R,
                   const float* __restrict__ G, const float* __restrict__ Bt,
                   float* __restrict__ Out, __half* __restrict__ Oh)
{
    const int N = E;
    int row = blockIdx.x;
    int tid = threadIdx.x;
    int lane = tid & 31, wid = tid >> 5;
    __shared__ float sm[8];
    __shared__ float stats[2];

    int idx = tid * 4;
    float4 xv = *(const float4*)(X + (size_t)row * N + idx);
    __half2 r01 = *(const __half2*)(R + (size_t)row * N + idx);
    __half2 r23 = *(const __half2*)(R + (size_t)row * N + idx + 2);
    float2 rf01 = __half22float2(r01);
    float2 rf23 = __half22float2(r23);
    float v0 = xv.x + rf01.x, v1 = xv.y + rf01.y;
    float v2 = xv.z + rf23.x, v3 = xv.w + rf23.y;

    float s = (v0 + v1) + (v2 + v3);
#pragma unroll
    for (int off = 16; off > 0; off >>= 1) s += __shfl_down_sync(0xffffffffu, s, off);
    if (lane == 0) sm[wid] = s;
    __syncthreads();
    if (tid == 0) {
        float t = 0.f;
#pragma unroll
        for (int i = 0; i < 8; i++) t += sm[i];
        stats[0] = t * (1.f / N);
    }
    __syncthreads();
    float mu = stats[0];

    float d0 = v0 - mu, d1 = v1 - mu, d2 = v2 - mu, d3 = v3 - mu;
    float vs = (d0 * d0 + d1 * d1) + (d2 * d2 + d3 * d3);
#pragma unroll
    for (int off = 16; off > 0; off >>= 1) vs += __shfl_down_sync(0xffffffffu, vs, off);
    __syncthreads();
    if (lane == 0) sm[wid] = vs;
    __syncthreads();
    if (tid == 0) {
        float t = 0.f;
#pragma unroll
        for (int i = 0; i < 8; i++) t += sm[i];
        stats[1] = rsqrtf(t * (1.f / N) + LN_EPS);
    }
    __syncthreads();
    float rstd = stats[1];

    float4 gv = *(const float4*)(G + idx);
    float4 bv = *(const float4*)(Bt + idx);
    float y0 = d0 * rstd * gv.x + bv.x;
    float y1 = d1 * rstd * gv.y + bv.y;
    float y2 = d2 * rstd * gv.z + bv.z;
    float y3 = d3 * rstd * gv.w + bv.w;
    *(float4*)(Out + (size_t)row * N + idx) = make_float4(y0, y1, y2, y3);
    if (Oh) {
        *(__half2*)(Oh + (size_t)row * N + idx)     = __floats2half2_rn(y0, y1);
        *(__half2*)(Oh + (size_t)row * N + idx + 2) = __floats2half2_rn(y2, y3);
    }
}

// ---------------------------------------------------------------------------
// Launch: side stream overlaps off-critical-path preprocessing.
// ---------------------------------------------------------------------------
extern "C" void kernel_launch(void* const* d_in, const int* in_sizes, int n_in,
                              void* d_out, int out_size)
{
    const float* x       = (const float*)d_in[0];
    const float* context = (const float*)d_in[1];
    const float* sa_wq = (const float*)d_in[2];
    const float* sa_wk = (const float*)d_in[3];
    const float* sa_wv = (const float*)d_in[4];
    const float* sa_wo = (const float*)d_in[5];
    const float* sa_bo = (const float*)d_in[6];
    const float* ca_wq = (const float*)d_in[7];
    const float* ca_wk = (const float*)d_in[8];
    const float* ca_wv = (const float*)d_in[9];
    const float* ca_wo = (const float*)d_in[10];
    const float* ca_bo = (const float*)d_in[11];
    const float* n1_g  = (const float*)d_in[12];
    const float* n1_b  = (const float*)d_in[13];
    const float* n2_g  = (const float*)d_in[14];
    const float* n2_b  = (const float*)d_in[15];
    const float* n3_g  = (const float*)d_in[16];
    const float* n3_b  = (const float*)d_in[17];
    const float* ff_w1 = (const float*)d_in[18];
    const float* ff_b1 = (const float*)d_in[19];
    const float* ff_w2 = (const float*)d_in[20];
    const float* ff_b2 = (const float*)d_in[21];
    float* out = (float*)d_out;

    float *x1f_, *x2f_;
    cudaGetSymbolAddress((void**)&x1f_, g_x1f);
    cudaGetSymbolAddress((void**)&x2f_, g_x2f);

    __half *tmph, *qh, *kh, *vh, *ath;
    cudaGetSymbolAddress((void**)&tmph, g_tmph);
    cudaGetSymbolAddress((void**)&qh,  g_qh);
    cudaGetSymbolAddress((void**)&kh,  g_kh);
    cudaGetSymbolAddress((void**)&vh,  g_vh);
    cudaGetSymbolAddress((void**)&ath, g_ath);

    __half *xh, *ctxh, *x1h, *x2h, *ffh;
    cudaGetSymbolAddress((void**)&xh,   g_xh);
    cudaGetSymbolAddress((void**)&ctxh, g_ctxh);
    cudaGetSymbolAddress((void**)&x1h,  g_x1h);
    cudaGetSymbolAddress((void**)&x2h,  g_x2h);
    cudaGetSymbolAddress((void**)&ffh,  g_ffh);

    __half *wqkv, *wqkvca, *wot, *cwot, *w1t, *w2t;
    cudaGetSymbolAddress((void**)&wqkv,   g_wqkv_sa);
    cudaGetSymbolAddress((void**)&wqkvca, g_wqkv_ca);
    cudaGetSymbolAddress((void**)&wot,    g_sa_wot);
    cudaGetSymbolAddress((void**)&cwot,   g_ca_wot);
    cudaGetSymbolAddress((void**)&w1t,    g_w1t);
    cudaGetSymbolAddress((void**)&w2t,    g_w2t);

    cudaFuncSetAttribute(hgemm1_kernel,
                         cudaFuncAttributeMaxDynamicSharedMemorySize, HG1_SMEM);

    // Side stream + events (host objects; no device allocation). Created per
    // call for determinism; destroyed after enqueue (graph holds the nodes).
    cudaStream_t s2;
    cudaStreamCreateWithFlags(&s2, cudaStreamNonBlocking);
    cudaEvent_t evF, evJ;
    cudaEventCreateWithFlags(&evF, cudaEventDisableTiming);
    cudaEventCreateWithFlags(&evJ, cudaEventDisableTiming);

    dim3 tB(32, 8);
    int nElem = M_ROWS * E;

    // Fork: side stream handles everything not needed until after SA FA.
    cudaEventRecord(evF, 0);
    cudaStreamWaitEvent(s2, evF, 0);
    {
        TP8 side;
        side.s[0] = sa_wo; side.d[0] = wot;
        side.s[1] = ca_wq; side.d[1] = wqkvca;
        side.s[2] = ca_wk; side.d[2] = wqkvca + E * E;
        side.s[3] = ca_wv; side.d[3] = wqkvca + 2 * E * E;
        side.s[4] = ca_wo; side.d[4] = cwot;
        transpose8_kernel<<<dim3(E / 32, E / 32, 5), tB, 0, s2>>>(side);
        transpose_ff_kernel<<<dim3(HID / 32, HID / 32, 2), tB, 0, s2>>>(ff_w1, w1t, ff_w2, w2t);
        conv1_h_kernel<<<nElem / 4096, 256, 0, s2>>>(context, ctxh, nElem);
        cudaEventRecord(evJ, s2);
    }

    // Main (critical) path: SA q/k/v weights + x convert only.
    {
        TP8 mainp;
        mainp.s[0] = sa_wq; mainp.d[0] = wqkv;
        mainp.s[1] = sa_wk; mainp.d[1] = wqkv + E * E;
        mainp.s[2] = sa_wv; mainp.d[2] = wqkv + 2 * E * E;
        transpose8_kernel<<<dim3(E / 32, E / 32, 3), tB>>>(mainp);
        conv1_h_kernel<<<nElem / 4096, 256>>>(x, xh, nElem);
    }

    dim3 gQKV(3 * E / 128, M_ROWS / 128);   // 24 x 32
    dim3 gE(E / 128, M_ROWS / 128);         // 8 x 32
    dim3 gH(HID / 128, M_ROWS / 128);       // 32 x 32
    dim3 gFA(BATCH * NH, T / 64);

    // ---- Self-attention ----
    hgemm1_kernel<<<gQKV, 256, HG1_SMEM>>>(xh, nullptr, 1 << 30, wqkv, nullptr, nullptr,
                                           qh, kh, vh, 8, E, 3 * E, E, 0);
    fa_mma_kernel<<<gFA, 128>>>(qh, kh, vh, ath, 1);

    // Join: side-stream outputs (wot, CA weights, FFN weights, ctxh) ready.
    cudaStreamWaitEvent(0, evJ, 0);

    hgemm1_kernel<<<gE, 256, HG1_SMEM>>>(ath, nullptr, 1 << 30, wot, sa_bo, nullptr,
                                         tmph, nullptr, nullptr, 8, E, E, E, 0);
    ln_residual_kernel<<<M_ROWS, 256>>>(x, tmph, n1_g, n1_b, x1f_, x1h);

    // ---- Cross-attention (q from x1h, k/v from ctxh; one launch) ----
    hgemm1_kernel<<<gQKV, 256, HG1_SMEM>>>(x1h, ctxh, 8, wqkvca, nullptr, nullptr,
                                           qh, kh, vh, 8, E, 3 * E, E, 0);
    fa_mma_kernel<<<gFA, 128>>>(qh, kh, vh, ath, 0);
    hgemm1_kernel<<<gE, 256, HG1_SMEM>>>(ath, nullptr, 1 << 30, cwot, ca_bo, nullptr,
                                         tmph, nullptr, nullptr, 8, E, E, E, 0);
    ln_residual_kernel<<<M_ROWS, 256>>>(x1f_, tmph, n2_g, n2_b, x2f_, x2h);

    // ---- FFN ----
    hgemm1_kernel<<<gH, 256, HG1_SMEM>>>(x2h, nullptr, 1 << 30, w1t, ff_b1, nullptr,
                                         ffh, nullptr, nullptr, 32, HID, HID, E, 1);
    hgemm1_kernel<<<gE, 256, HG1_SMEM>>>(ffh, nullptr, 1 << 30, w2t, ff_b2, nullptr,
                                         tmph, nullptr, nullptr, 8, E, E, HID, 0);
    ln_residual_kernel<<<M_ROWS, 256>>>(x2f_, tmph, n3_g, n3_b, out, nullptr);

    // Cleanup of host handles (nodes already recorded in the graph).
    cudaEventDestroy(evF);
    cudaEventDestroy(evJ);
    cudaStreamDestroy(s2);
}

// round 14
// speedup vs baseline: 1.0844x; 1.0551x over previous
#include <cuda_runtime.h>
#include <cuda_fp16.h>
#include <math.h>
#include <stdint.h>

// Problem constants
#define BATCH 4
#define T 1024
#define E 1024
#define NH 16
#define HS 64
#define HID 4096
#define M_ROWS (BATCH * T)   // 4096
#define LN_EPS 1e-5f
#define ATT_SCALE 0.03125f   // E^-0.25 on q and k each -> E^-0.5 on dot
#define LOG2E 1.4426950408889634f

// ---------------------------------------------------------------------------
// Scratch (__device__ globals; no allocation allowed)
// ---------------------------------------------------------------------------
__device__ float  g_x1f[M_ROWS * E];
__device__ float  g_x2f[M_ROWS * E];
__device__ __half g_tmph[M_ROWS * E];
__device__ __half g_qh[M_ROWS * E], g_kh[M_ROWS * E], g_vh[M_ROWS * E];
__device__ __half g_ath[M_ROWS * E];
__device__ __half g_xh[M_ROWS * E];
__device__ __half g_ctxh[M_ROWS * E];
__device__ __half g_x1h[M_ROWS * E];
__device__ __half g_x2h[M_ROWS * E];
__device__ __half g_ffh[M_ROWS * HID];
// fp16 transposed weights [N,K] (QKV packed for fused projections)
__device__ __half g_wqkv_sa[3 * E * E];         // wq^T | wk^T | wv^T
__device__ __half g_wqkv_ca[3 * E * E];         // wq^T | wk^T | wv^T
__device__ __half g_sa_wot[E * E], g_ca_wot[E * E];
__device__ __half g_w1t[HID * E], g_w2t[E * HID];

// ---------------------------------------------------------------------------
// PTX helpers (sm_80+-compatible: cp.async, ldmatrix, mma.sync)
// ---------------------------------------------------------------------------
__device__ __forceinline__ uint32_t smem_u32(const void* p) {
    uint32_t a;
    asm("{ .reg .u64 t; cvta.to.shared.u64 t, %1; cvt.u32.u64 %0, t; }"
        : "=r"(a) : "l"(p));
    return a;
}

#define CP_ASYNC16(saddr, gptr) \
    asm volatile("cp.async.cg.shared.global [%0], [%1], 16;" \
        :: "r"(saddr), "l"(gptr) : "memory")
#define CP_COMMIT()  asm volatile("cp.async.commit_group;" ::: "memory")
#define CP_WAIT0()   asm volatile("cp.async.wait_group 0;" ::: "memory")
#define CP_WAIT1()   asm volatile("cp.async.wait_group 1;" ::: "memory")

#define LDSM4(r, addr) \
    asm volatile("ldmatrix.sync.aligned.m8n8.x4.shared.b16 {%0,%1,%2,%3}, [%4];" \
        : "=r"((r)[0]), "=r"((r)[1]), "=r"((r)[2]), "=r"((r)[3]) : "r"(addr))
#define LDSM2(r, addr) \
    asm volatile("ldmatrix.sync.aligned.m8n8.x2.shared.b16 {%0,%1}, [%2];" \
        : "=r"((r)[0]), "=r"((r)[1]) : "r"(addr))
#define LDSM4T(r, addr) \
    asm volatile("ldmatrix.sync.aligned.m8n8.x4.trans.shared.b16 {%0,%1,%2,%3}, [%4];" \
        : "=r"((r)[0]), "=r"((r)[1]), "=r"((r)[2]), "=r"((r)[3]) : "r"(addr))

__device__ __forceinline__ void mma16816(float* c, const uint32_t* a, const uint32_t* b) {
    asm volatile(
        "mma.sync.aligned.m16n8k16.row.col.f32.f16.f16.f32 "
        "{%0,%1,%2,%3}, {%4,%5,%6,%7}, {%8,%9}, {%0,%1,%2,%3};"
        : "+f"(c[0]), "+f"(c[1]), "+f"(c[2]), "+f"(c[3])
        : "r"(a[0]), "r"(a[1]), "r"(a[2]), "r"(a[3]), "r"(b[0]), "r"(b[1]));
}

// ===========================================================================
// Single-plane HGEMM (R7 version — known good): C = A[M,K] @ Bt[N,K]^T
// (+bias)(+relu). A selected per N-tile: bx < a2Start -> Ah, else A2.
// Output: fp32 C32 OR fp16 into up to 3 dest buffers (bx/dstTiles, ld outLd).
// Tile 128x128x64, 256 threads, 3-stage cp.async (96KB smem, 2 CTA/SM),
// single __syncthreads per ktile.
// ===========================================================================
#define HG1_STAGE 32768
#define HG1_SMEM  (3 * HG1_STAGE)

__global__ void __launch_bounds__(256, 2)
hgemm1_kernel(const __half* __restrict__ Ah, const __half* __restrict__ A2,
              int a2Start,
              const __half* __restrict__ Bt, const float* __restrict__ bias,
              float* __restrict__ C32,
              __half* __restrict__ D0, __half* __restrict__ D1, __half* __restrict__ D2,
              int dstTiles, int outLd, int N, int K, int relu)
{
    extern __shared__ char smem[];
    uint32_t sb = smem_u32(smem);
    int tid = threadIdx.x;
    int lane = tid & 31;
    int wid = tid >> 5;
    int wm = wid & 1, wn = wid >> 1;
    int bx = blockIdx.x, by = blockIdx.y;

    const __half* Abase = (bx < a2Start) ? Ah : A2;
    const __half* gA = Abase + (size_t)by * 128 * K;
    const __half* gB = Bt + (size_t)bx * 128 * K;

    int lrow = tid >> 3;
    int lch = tid & 7;
    uint32_t soff[4];
#pragma unroll
    for (int i = 0; i < 4; i++) {
        int r = lrow + 32 * i;
        soff[i] = (uint32_t)(r * 128 + ((lch ^ (r & 7)) * 16));
    }

    uint32_t aOff[4], aX[4], bOff[4], bX[4];
#pragma unroll
    for (int mf = 0; mf < 4; mf++) {
        int r = wm * 64 + mf * 16 + (lane & 15);
        aOff[mf] = r * 128; aX[mf] = r & 7;
    }
#pragma unroll
    for (int nf = 0; nf < 4; nf++) {
        int r = wn * 32 + nf * 8 + (lane & 7);
        bOff[nf] = r * 128; bX[nf] = r & 7;
    }
    int aSel = lane >> 4;
    int bSel = (lane >> 3) & 1;

    float acc[4][4][4];
#pragma unroll
    for (int mf = 0; mf < 4; mf++)
#pragma unroll
        for (int nf = 0; nf < 4; nf++)
#pragma unroll
            for (int r = 0; r < 4; r++) acc[mf][nf][r] = 0.f;

    const int KT = K >> 6;

    // Prologue: stage ktiles 0 and 1 into buffers 0 and 1
#pragma unroll
    for (int p = 0; p < 2; p++) {
        uint32_t st = sb + p * HG1_STAGE;
        int k0 = p << 6;
#pragma unroll
        for (int i = 0; i < 4; i++) {
            int r = lrow + 32 * i;
            CP_ASYNC16(st + soff[i],         gA + (size_t)r * K + k0 + lch * 8);
            CP_ASYNC16(st + 16384 + soff[i], gB + (size_t)r * K + k0 + lch * 8);
        }
        CP_COMMIT();
    }

    int cur = 0;   // buffer for current ktile
    int pf = 2;    // buffer for ktile kt+2
    for (int kt = 0; kt < KT; kt++) {
        if (kt + 2 < KT) { CP_WAIT1(); } else { CP_WAIT0(); }
        __syncthreads();

        if (kt + 2 < KT) {
            uint32_t st = sb + pf * HG1_STAGE;
            int k0 = (kt + 2) << 6;
#pragma unroll
            for (int i = 0; i < 4; i++) {
                int r = lrow + 32 * i;
                CP_ASYNC16(st + soff[i],         gA + (size_t)r * K + k0 + lch * 8);
                CP_ASYNC16(st + 16384 + soff[i], gB + (size_t)r * K + k0 + lch * 8);
            }
            CP_COMMIT();
        }

        uint32_t aBase = sb + cur * HG1_STAGE;
        uint32_t bBase = aBase + 16384;

#pragma unroll
        for (int ks = 0; ks < 4; ks++) {
            int cA = ks * 2 + aSel;
            int cB = ks * 2 + bSel;
            uint32_t a[4][4], b[4][2];
#pragma unroll
            for (int mf = 0; mf < 4; mf++)
                LDSM4(a[mf], aBase + aOff[mf] + ((cA ^ aX[mf]) << 4));
#pragma unroll
            for (int nf = 0; nf < 4; nf++)
                LDSM2(b[nf], bBase + bOff[nf] + ((cB ^ bX[nf]) << 4));
#pragma unroll
            for (int mf = 0; mf < 4; mf++)
#pragma unroll
                for (int nf = 0; nf < 4; nf++)
                    mma16816(acc[mf][nf], a[mf], b[nf]);
        }

        cur = (cur == 2) ? 0 : cur + 1;
        pf  = (pf == 2) ? 0 : pf + 1;
    }

    int g = lane >> 2, tig = lane & 3;
    int which = bx / dstTiles;
    int lbx = bx - which * dstTiles;
    __half* D = (which == 0) ? D0 : ((which == 1) ? D1 : D2);
#pragma unroll
    for (int mf = 0; mf < 4; mf++) {
#pragma unroll
        for (int nf = 0; nf < 4; nf++) {
            int r0 = by * 128 + wm * 64 + mf * 16 + g;
            int cl = wn * 32 + nf * 8 + tig * 2;
            int cglob = bx * 128 + cl;
            float b0 = 0.f, b1 = 0.f;
            if (bias) { b0 = bias[cglob]; b1 = bias[cglob + 1]; }
            float v0 = acc[mf][nf][0] + b0, v1 = acc[mf][nf][1] + b1;
            float v2 = acc[mf][nf][2] + b0, v3 = acc[mf][nf][3] + b1;
            if (relu) {
                v0 = fmaxf(v0, 0.f); v1 = fmaxf(v1, 0.f);
                v2 = fmaxf(v2, 0.f); v3 = fmaxf(v3, 0.f);
            }
            if (C32) {
                *(float2*)(C32 + (size_t)r0 * N + cglob) = make_float2(v0, v1);
                *(float2*)(C32 + (size_t)(r0 + 8) * N + cglob) = make_float2(v2, v3);
            } else {
                int c = lbx * 128 + cl;
                *(__half2*)(D + (size_t)r0 * outLd + c) = __floats2half2_rn(v0, v1);
                *(__half2*)(D + (size_t)(r0 + 8) * outLd + c) = __floats2half2_rn(v2, v3);
            }
        }
    }
}

// ---------------------------------------------------------------------------
// Tensor-core flash attention (R7 version — known good).
// grid (BATCH*NH, T/64), 128 threads. log2-domain softmax.
// ---------------------------------------------------------------------------
__global__ void __launch_bounds__(128)
fa_mma_kernel(const __half* __restrict__ Qm, const __half* __restrict__ Km,
              const __half* __restrict__ Vm, __half* __restrict__ Oh, int causal)
{
    __shared__ __half sQ[64 * 64];
    __shared__ __half sK[2][64 * 64];
    __shared__ __half sV[2][64 * 64];

    int tid = threadIdx.x, lane = tid & 31, w = tid >> 5;
    int g = lane >> 2, tig = lane & 3;
    int bh = blockIdx.x, b = bh >> 4, h = bh & 15;
    int qt = blockIdx.y;

    uint32_t sq = smem_u32(sQ);
    uint32_t skb[2] = { smem_u32(sK[0]), smem_u32(sK[1]) };
    uint32_t svb[2] = { smem_u32(sV[0]), smem_u32(sV[1]) };

    const __half* Qg = Qm + ((size_t)(b * T + qt * 64)) * E + h * HS;
    const __half* K0 = Km + ((size_t)(b * T)) * E + h * HS;
    const __half* V0 = Vm + ((size_t)(b * T)) * E + h * HS;

#pragma unroll
    for (int i = 0; i < 4; i++) {
        int c = tid + i * 128; int r = c >> 3; int ch = c & 7;
        uint32_t off = r * 128 + ((ch ^ (r & 7)) << 4);
        CP_ASYNC16(sq + off, Qg + (size_t)r * E + ch * 8);
        CP_ASYNC16(skb[0] + off, K0 + (size_t)r * E + ch * 8);
        CP_ASYNC16(svb[0] + off, V0 + (size_t)r * E + ch * 8);
    }
    CP_COMMIT();
    CP_WAIT0();
    __syncthreads();

    uint32_t qf[4][4];
    {
        int r = w * 16 + (lane & 15); int sel = lane >> 4; int rx = r & 7;
        uint32_t ro = sq + r * 128;
#pragma unroll
        for (int ks = 0; ks < 4; ks++)
            LDSM4(qf[ks], ro + (((2 * ks + sel) ^ rx) << 4));
    }

    float oacc[8][4];
#pragma unroll
    for (int n = 0; n < 8; n++)
#pragma unroll
        for (int e = 0; e < 4; e++) oacc[n][e] = 0.f;
    float m0 = -1e30f, m1 = -1e30f, l0 = 0.f, l1 = 0.f;

    int nk = causal ? (qt + 1) : (T / 64);
    const float SC2 = ATT_SCALE * LOG2E;   // scores in log2 domain

    for (int kt = 0; kt < nk; kt++) {
        int cur = kt & 1;
        if (kt + 1 < nk) {
            int nst = cur ^ 1;
            const __half* Kg = Km + ((size_t)(b * T + (kt + 1) * 64)) * E + h * HS;
            const __half* Vg = Vm + ((size_t)(b * T + (kt + 1) * 64)) * E + h * HS;
#pragma unroll
            for (int i = 0; i < 4; i++) {
                int c = tid + i * 128; int r = c >> 3; int ch = c & 7;
                uint32_t off = r * 128 + ((ch ^ (r & 7)) << 4);
                CP_ASYNC16(skb[nst] + off, Kg + (size_t)r * E + ch * 8);
                CP_ASYNC16(svb[nst] + off, Vg + (size_t)r * E + ch * 8);
            }
            CP_COMMIT();
        }

        float sacc[8][4];
#pragma unroll
        for (int n = 0; n < 8; n++)
#pragma unroll
            for (int e = 0; e < 4; e++) sacc[n][e] = 0.f;

        uint32_t skc = skb[cur], svc = svb[cur];
#pragma unroll
        for (int ks = 0; ks < 4; ks++) {
            uint32_t kb[8][2];
            int rl = lane & 7, sel = (lane >> 3) & 1;
#pragma unroll
            for (int n = 0; n < 8; n++) {
                int rr = n * 8 + rl;
                LDSM2(kb[n], skc + rr * 128 + (((2 * ks + sel) ^ (rr & 7)) << 4));
            }
#pragma unroll
            for (int n = 0; n < 8; n++) mma16816(sacc[n], qf[ks], kb[n]);
        }

#pragma unroll
        for (int n = 0; n < 8; n++)
#pragma unroll
            for (int e = 0; e < 4; e++) sacc[n][e] *= SC2;
        if (causal && kt == qt) {
            int row0 = w * 16 + g;
#pragma unroll
            for (int n = 0; n < 8; n++) {
                int c0 = n * 8 + tig * 2;
                if (c0     > row0)     sacc[n][0] = -1e30f;
                if (c0 + 1 > row0)     sacc[n][1] = -1e30f;
                if (c0     > row0 + 8) sacc[n][2] = -1e30f;
                if (c0 + 1 > row0 + 8) sacc[n][3] = -1e30f;
            }
        }

        float mx0 = -1e30f, mx1 = -1e30f;
#pragma unroll
        for (int n = 0; n < 8; n++) {
            mx0 = fmaxf(mx0, fmaxf(sacc[n][0], sacc[n][1]));
            mx1 = fmaxf(mx1, fmaxf(sacc[n][2], sacc[n][3]));
        }
        mx0 = fmaxf(mx0, __shfl_xor_sync(0xffffffffu, mx0, 1));
        mx0 = fmaxf(mx0, __shfl_xor_sync(0xffffffffu, mx0, 2));
        mx1 = fmaxf(mx1, __shfl_xor_sync(0xffffffffu, mx1, 1));
        mx1 = fmaxf(mx1, __shfl_xor_sync(0xffffffffu, mx1, 2));
        float mn0 = fmaxf(m0, mx0), mn1 = fmaxf(m1, mx1);
        float a0 = exp2f(m0 - mn0), a1 = exp2f(m1 - mn1);
        m0 = mn0; m1 = mn1;

        float ps0 = 0.f, ps1 = 0.f;
        uint32_t pfr[4][4];
#pragma unroll
        for (int n = 0; n < 8; n++) {
            float p0 = exp2f(sacc[n][0] - mn0), p1 = exp2f(sacc[n][1] - mn0);
            float p2 = exp2f(sacc[n][2] - mn1), p3 = exp2f(sacc[n][3] - mn1);
            ps0 += p0 + p1; ps1 += p2 + p3;
            __half2 h01 = __floats2half2_rn(p0, p1);
            __half2 h23 = __floats2half2_rn(p2, p3);
            int ks = n >> 1, hi = (n & 1) * 2;
            pfr[ks][hi]     = *(uint32_t*)&h01;
            pfr[ks][hi + 1] = *(uint32_t*)&h23;
        }
        l0 = l0 * a0 + ps0;
        l1 = l1 * a1 + ps1;
#pragma unroll
        for (int n = 0; n < 8; n++) {
            oacc[n][0] *= a0; oacc[n][1] *= a0;
            oacc[n][2] *= a1; oacc[n][3] *= a1;
        }

        {
            int rl = lane & 15, cs = lane >> 4;
#pragma unroll
            for (int np = 0; np < 4; np++) {
#pragma unroll
                for (int ks = 0; ks < 4; ks++) {
                    uint32_t vb[4];
                    int rr = ks * 16 + rl;
                    int ch = np * 2 + cs;
                    LDSM4T(vb, svc + rr * 128 + ((ch ^ (rr & 7)) << 4));
                    mma16816(oacc[2 * np],     pfr[ks], vb);
                    mma16816(oacc[2 * np + 1], pfr[ks], vb + 2);
                }
            }
        }

        CP_WAIT0();
        __syncthreads();
    }

    l0 += __shfl_xor_sync(0xffffffffu, l0, 1);
    l0 += __shfl_xor_sync(0xffffffffu, l0, 2);
    l1 += __shfl_xor_sync(0xffffffffu, l1, 1);
    l1 += __shfl_xor_sync(0xffffffffu, l1, 2);
    float i0 = 1.f / l0, i1 = 1.f / l1;

    size_t base0 = ((size_t)(b * T + qt * 64 + w * 16 + g)) * E + h * HS;
    size_t base1 = base0 + (size_t)8 * E;
#pragma unroll
    for (int n = 0; n < 8; n++) {
        int c = n * 8 + tig * 2;
        *(__half2*)(Oh + base0 + c) = __floats2half2_rn(oacc[n][0] * i0, oacc[n][1] * i0);
        *(__half2*)(Oh + base1 + c) = __floats2half2_rn(oacc[n][2] * i1, oacc[n][3] * i1);
    }
}

// ---------------------------------------------------------------------------
// Fast batched weight transpose to fp16: 64x64 tiles, float4 loads,
// half2-pair stores, 4 tiles of work per thread each phase.
// Matrices are E x E; count = gridDim.z.
// ---------------------------------------------------------------------------
struct TP8 { const float* s[8]; __half* d[8]; };

__global__ void __launch_bounds__(256)
transpose64_kernel(TP8 p)
{
    __shared__ float t[64][65];
    const float* in = p.s[blockIdx.z];
    __half* out = p.d[blockIdx.z];
    int bx = blockIdx.x * 64, by = blockIdx.y * 64;
    int tx = threadIdx.x & 15, ty = threadIdx.x >> 4;

#pragma unroll
    for (int j = 0; j < 4; j++) {
        int r = ty + j * 16;
        float4 v = *(const float4*)(in + (size_t)(by + r) * E + bx + tx * 4);
        t[tx * 4 + 0][r] = v.x;
        t[tx * 4 + 1][r] = v.y;
        t[tx * 4 + 2][r] = v.z;
        t[tx * 4 + 3][r] = v.w;
    }
    __syncthreads();
#pragma unroll
    for (int j = 0; j < 4; j++) {
        int c = ty + j * 16;
        __half2 h0 = __floats2half2_rn(t[c][tx * 4 + 0], t[c][tx * 4 + 1]);
        __half2 h1 = __floats2half2_rn(t[c][tx * 4 + 2], t[c][tx * 4 + 3]);
        *(__half2*)(out + (size_t)(bx + c) * E + by + tx * 4)     = h0;
        *(__half2*)(out + (size_t)(bx + c) * E + by + tx * 4 + 2) = h1;
    }
}

// FFN weight transposes (z=0: w1 [E,HID]->[HID,E]; z=1: w2 [HID,E]->[E,HID]),
// same 64x64 fast scheme; grid sized for the larger matrix with masking.
__global__ void __launch_bounds__(256)
transpose_ff_kernel(const float* __restrict__ w1, __half* __restrict__ w1t,
                    const float* __restrict__ w2, __half* __restrict__ w2t)
{
    __shared__ float t[64][65];
    const float* in;  __half* out;  int R, C;
    if (blockIdx.z == 0) { in = w1; out = w1t; R = E;  C = HID; }
    else                 { in = w2; out = w2t; R = HID; C = E;  }
    int bx = blockIdx.x * 64, by = blockIdx.y * 64;
    if (bx >= C || by >= R) return;
    int tx = threadIdx.x & 15, ty = threadIdx.x >> 4;

#pragma unroll
    for (int j = 0; j < 4; j++) {
        int r = ty + j * 16;
        float4 v = *(const float4*)(in + (size_t)(by + r) * C + bx + tx * 4);
        t[tx * 4 + 0][r] = v.x;
        t[tx * 4 + 1][r] = v.y;
        t[tx * 4 + 2][r] = v.z;
        t[tx * 4 + 3][r] = v.w;
    }
    __syncthreads();
#pragma unroll
    for (int j = 0; j < 4; j++) {
        int c = ty + j * 16;
        __half2 h0 = __floats2half2_rn(t[c][tx * 4 + 0], t[c][tx * 4 + 1]);
        __half2 h1 = __floats2half2_rn(t[c][tx * 4 + 2], t[c][tx * 4 + 3]);
        *(__half2*)(out + (size_t)(bx + c) * R + by + tx * 4)     = h0;
        *(__half2*)(out + (size_t)(bx + c) * R + by + tx * 4 + 2) = h1;
    }
}

// ---------------------------------------------------------------------------
// Single fp32 -> fp16 convert, 4 float4s per thread
// ---------------------------------------------------------------------------
__global__ void __launch_bounds__(256)
conv1_h_kernel(const float* __restrict__ src, __half* __restrict__ dst, int n)
{
    int base = (blockIdx.x * 256 + threadIdx.x) * 4;
    int stride = gridDim.x * 256 * 4;
#pragma unroll
    for (int k = 0; k < 4; k++) {
        int i = base + k * stride;
        if (i < n) {
            float4 v = *(const float4*)(src + i);
            *(__half2*)(dst + i)     = __floats2half2_rn(v.x, v.y);
            *(__half2*)(dst + i + 2) = __floats2half2_rn(v.z, v.w);
        }
    }
}

// ---------------------------------------------------------------------------
// Fused residual + LayerNorm, fp16 residual input (+ optional fp16 plane)
// ---------------------------------------------------------------------------
__global__ void __launch_bounds__(256)
ln_residual_kernel(const float* __restrict__ X, const __half* __restrict__ R,
                   const float* __restrict__ G, const float* __restrict__ Bt,
                   float* __restrict__ Out, __half* __restrict__ Oh)
{
    const int N = E;
    int row = blockIdx.x;
    int tid = threadIdx.x;
    int lane = tid & 31, wid = tid >> 5;
    __shared__ float sm[8];
    __shared__ float stats[2];

    int idx = tid * 4;
    float4 xv = *(const float4*)(X + (size_t)row * N + idx);
    __half2 r01 = *(const __half2*)(R + (size_t)row * N + idx);
    __half2 r23 = *(const __half2*)(R + (size_t)row * N + idx + 2);
    float2 rf01 = __half22float2(r01);
    float2 rf23 = __half22float2(r23);
    float v0 = xv.x + rf01.x, v1 = xv.y + rf01.y;
    float v2 = xv.z + rf23.x, v3 = xv.w + rf23.y;

    float s = (v0 + v1) + (v2 + v3);
#pragma unroll
    for (int off = 16; off > 0; off >>= 1) s += __shfl_down_sync(0xffffffffu, s, off);
    if (lane == 0) sm[wid] = s;
    __syncthreads();
    if (tid == 0) {
        float t = 0.f;
#pragma unroll
        for (int i = 0; i < 8; i++) t += sm[i];
        stats[0] = t * (1.f / N);
    }
    __syncthreads();
    float mu = stats[0];

    float d0 = v0 - mu, d1 = v1 - mu, d2 = v2 - mu, d3 = v3 - mu;
    float vs = (d0 * d0 + d1 * d1) + (d2 * d2 + d3 * d3);
#pragma unroll
    for (int off = 16; off > 0; off >>= 1) vs += __shfl_down_sync(0xffffffffu, vs, off);
    __syncthreads();
    if (lane == 0) sm[wid] = vs;
    __syncthreads();
    if (tid == 0) {
        float t = 0.f;
#pragma unroll
        for (int i = 0; i < 8; i++) t += sm[i];
        stats[1] = rsqrtf(t * (1.f / N) + LN_EPS);
    }
    __syncthreads();
    float rstd = stats[1];

    float4 gv = *(const float4*)(G + idx);
    float4 bv = *(const float4*)(Bt + idx);
    float y0 = d0 * rstd * gv.x + bv.x;
    float y1 = d1 * rstd * gv.y + bv.y;
    float y2 = d2 * rstd * gv.z + bv.z;
    float y3 = d3 * rstd * gv.w + bv.w;
    *(float4*)(Out + (size_t)row * N + idx) = make_float4(y0, y1, y2, y3);
    if (Oh) {
        *(__half2*)(Oh + (size_t)row * N + idx)     = __floats2half2_rn(y0, y1);
        *(__half2*)(Oh + (size_t)row * N + idx + 2) = __floats2half2_rn(y2, y3);
    }
}

// ---------------------------------------------------------------------------
// Launch: side stream overlaps off-critical-path preprocessing.
// ---------------------------------------------------------------------------
extern "C" void kernel_launch(void* const* d_in, const int* in_sizes, int n_in,
                              void* d_out, int out_size)
{
    const float* x       = (const float*)d_in[0];
    const float* context = (const float*)d_in[1];
    const float* sa_wq = (const float*)d_in[2];
    const float* sa_wk = (const float*)d_in[3];
    const float* sa_wv = (const float*)d_in[4];
    const float* sa_wo = (const float*)d_in[5];
    const float* sa_bo = (const float*)d_in[6];
    const float* ca_wq = (const float*)d_in[7];
    const float* ca_wk = (const float*)d_in[8];
    const float* ca_wv = (const float*)d_in[9];
    const float* ca_wo = (const float*)d_in[10];
    const float* ca_bo = (const float*)d_in[11];
    const float* n1_g  = (const float*)d_in[12];
    const float* n1_b  = (const float*)d_in[13];
    const float* n2_g  = (const float*)d_in[14];
    const float* n2_b  = (const float*)d_in[15];
    const float* n3_g  = (const float*)d_in[16];
    const float* n3_b  = (const float*)d_in[17];
    const float* ff_w1 = (const float*)d_in[18];
    const float* ff_b1 = (const float*)d_in[19];
    const float* ff_w2 = (const float*)d_in[20];
    const float* ff_b2 = (const float*)d_in[21];
    float* out = (float*)d_out;

    float *x1f_, *x2f_;
    cudaGetSymbolAddress((void**)&x1f_, g_x1f);
    cudaGetSymbolAddress((void**)&x2f_, g_x2f);

    __half *tmph, *qh, *kh, *vh, *ath;
    cudaGetSymbolAddress((void**)&tmph, g_tmph);
    cudaGetSymbolAddress((void**)&qh,  g_qh);
    cudaGetSymbolAddress((void**)&kh,  g_kh);
    cudaGetSymbolAddress((void**)&vh,  g_vh);
    cudaGetSymbolAddress((void**)&ath, g_ath);

    __half *xh, *ctxh, *x1h, *x2h, *ffh;
    cudaGetSymbolAddress((void**)&xh,   g_xh);
    cudaGetSymbolAddress((void**)&ctxh, g_ctxh);
    cudaGetSymbolAddress((void**)&x1h,  g_x1h);
    cudaGetSymbolAddress((void**)&x2h,  g_x2h);
    cudaGetSymbolAddress((void**)&ffh,  g_ffh);

    __half *wqkv, *wqkvca, *wot, *cwot, *w1t, *w2t;
    cudaGetSymbolAddress((void**)&wqkv,   g_wqkv_sa);
    cudaGetSymbolAddress((void**)&wqkvca, g_wqkv_ca);
    cudaGetSymbolAddress((void**)&wot,    g_sa_wot);
    cudaGetSymbolAddress((void**)&cwot,   g_ca_wot);
    cudaGetSymbolAddress((void**)&w1t,    g_w1t);
    cudaGetSymbolAddress((void**)&w2t,    g_w2t);

    cudaFuncSetAttribute(hgemm1_kernel,
                         cudaFuncAttributeMaxDynamicSharedMemorySize, HG1_SMEM);

    // Side stream + events (host objects; no device allocation).
    cudaStream_t s2;
    cudaStreamCreateWithFlags(&s2, cudaStreamNonBlocking);
    cudaEvent_t evF, evJ;
    cudaEventCreateWithFlags(&evF, cudaEventDisableTiming);
    cudaEventCreateWithFlags(&evJ, cudaEventDisableTiming);

    int nElem = M_ROWS * E;

    // Fork: side stream handles everything not needed until after SA FA.
    cudaEventRecord(evF, 0);
    cudaStreamWaitEvent(s2, evF, 0);
    {
        TP8 side;
        side.s[0] = sa_wo; side.d[0] = wot;
        side.s[1] = ca_wq; side.d[1] = wqkvca;
        side.s[2] = ca_wk; side.d[2] = wqkvca + E * E;
        side.s[3] = ca_wv; side.d[3] = wqkvca + 2 * E * E;
        side.s[4] = ca_wo; side.d[4] = cwot;
        transpose64_kernel<<<dim3(E / 64, E / 64, 5), 256, 0, s2>>>(side);
        transpose_ff_kernel<<<dim3(HID / 64, HID / 64, 2), 256, 0, s2>>>(ff_w1, w1t, ff_w2, w2t);
        conv1_h_kernel<<<nElem / 4096, 256, 0, s2>>>(context, ctxh, nElem);
        cudaEventRecord(evJ, s2);
    }

    // Main (critical) path: SA q/k/v weights + x convert only.
    {
        TP8 mainp;
        mainp.s[0] = sa_wq; mainp.d[0] = wqkv;
        mainp.s[1] = sa_wk; mainp.d[1] = wqkv + E * E;
        mainp.s[2] = sa_wv; mainp.d[2] = wqkv + 2 * E * E;
        transpose64_kernel<<<dim3(E / 64, E / 64, 3), 256>>>(mainp);
        conv1_h_kernel<<<nElem / 4096, 256>>>(x, xh, nElem);
    }

    dim3 gQKV(3 * E / 128, M_ROWS / 128);   // 24 x 32
    dim3 gE(E / 128, M_ROWS / 128);         // 8 x 32
    dim3 gH(HID / 128, M_ROWS / 128);       // 32 x 32
    dim3 gFA(BATCH * NH, T / 64);

    // ---- Self-attention ----
    hgemm1_kernel<<<gQKV, 256, HG1_SMEM>>>(xh, nullptr, 1 << 30, wqkv, nullptr, nullptr,
                                           qh, kh, vh, 8, E, 3 * E, E, 0);
    fa_mma_kernel<<<gFA, 128>>>(qh, kh, vh, ath, 1);

    // Join: side-stream outputs ready before SA-wo GEMM.
    cudaStreamWaitEvent(0, evJ, 0);

    hgemm1_kernel<<<gE, 256, HG1_SMEM>>>(ath, nullptr, 1 << 30, wot, sa_bo, nullptr,
                                         tmph, nullptr, nullptr, 8, E, E, E, 0);
    ln_residual_kernel<<<M_ROWS, 256>>>(x, tmph, n1_g, n1_b, x1f_, x1h);

    // ---- Cross-attention (q from x1h, k/v from ctxh; one launch) ----
    hgemm1_kernel<<<gQKV, 256, HG1_SMEM>>>(x1h, ctxh, 8, wqkvca, nullptr, nullptr,
                                           qh, kh, vh, 8, E, 3 * E, E, 0);
    fa_mma_kernel<<<gFA, 128>>>(qh, kh, vh, ath, 0);
    hgemm1_kernel<<<gE, 256, HG1_SMEM>>>(ath, nullptr, 1 << 30, cwot, ca_bo, nullptr,
                                         tmph, nullptr, nullptr, 8, E, E, E, 0);
    ln_residual_kernel<<<M_ROWS, 256>>>(x1f_, tmph, n2_g, n2_b, x2f_, x2h);

    // ---- FFN ----
    hgemm1_kernel<<<gH, 256, HG1_SMEM>>>(x2h, nullptr, 1 << 30, w1t, ff_b1, nullptr,
                                         ffh, nullptr, nullptr, 32, HID, HID, E, 1);
    hgemm1_kernel<<<gE, 256, HG1_SMEM>>>(ffh, nullptr, 1 << 30, w2t, ff_b2, nullptr,
                                         tmph, nullptr, nullptr, 8, E, E, HID, 0);
    ln_residual_kernel<<<M_ROWS, 256>>>(x2f_, tmph, n3_g, n3_b, out, nullptr);

    // Cleanup of host handles (nodes already recorded in the graph).
    cudaEventDestroy(evF);
    cudaEventDestroy(evJ);
    cudaStreamDestroy(s2);
}

// round 15
// speedup vs baseline: 1.1134x; 1.0267x over previous
#include <cuda_runtime.h>
#include <cuda_fp16.h>
#include <math.h>
#include <stdint.h>

// Problem constants
#define BATCH 4
#define T 1024
#define E 1024
#define NH 16
#define HS 64
#define HID 4096
#define M_ROWS (BATCH * T)   // 4096
#define LN_EPS 1e-5f
#define ATT_SCALE 0.03125f   // E^-0.25 on q and k each -> E^-0.5 on dot
#define LOG2E 1.4426950408889634f

// ---------------------------------------------------------------------------
// Scratch (__device__ globals; no allocation allowed)
// ---------------------------------------------------------------------------
__device__ float  g_x1f[M_ROWS * E];
__device__ float  g_x2f[M_ROWS * E];
__device__ __half g_tmph[M_ROWS * E];
__device__ __half g_qh[M_ROWS * E], g_kh[M_ROWS * E], g_vh[M_ROWS * E];
__device__ __half g_kh2[M_ROWS * E], g_vh2[M_ROWS * E];   // CA k/v (side stream)
__device__ __half g_ath[M_ROWS * E];
__device__ __half g_xh[M_ROWS * E];
__device__ __half g_ctxh[M_ROWS * E];
__device__ __half g_x1h[M_ROWS * E];
__device__ __half g_x2h[M_ROWS * E];
__device__ __half g_ffh[M_ROWS * HID];
// fp16 transposed weights [N,K] (QKV packed for fused projections)
__device__ __half g_wqkv_sa[3 * E * E];         // wq^T | wk^T | wv^T
__device__ __half g_wqkv_ca[3 * E * E];         // wq^T | wk^T | wv^T
__device__ __half g_sa_wot[E * E], g_ca_wot[E * E];
__device__ __half g_w1t[HID * E], g_w2t[E * HID];

// ---------------------------------------------------------------------------
// PTX helpers (sm_80+-compatible: cp.async, ldmatrix, mma.sync)
// ---------------------------------------------------------------------------
__device__ __forceinline__ uint32_t smem_u32(const void* p) {
    uint32_t a;
    asm("{ .reg .u64 t; cvta.to.shared.u64 t, %1; cvt.u32.u64 %0, t; }"
        : "=r"(a) : "l"(p));
    return a;
}

#define CP_ASYNC16(saddr, gptr) \
    asm volatile("cp.async.cg.shared.global [%0], [%1], 16;" \
        :: "r"(saddr), "l"(gptr) : "memory")
#define CP_COMMIT()  asm volatile("cp.async.commit_group;" ::: "memory")
#define CP_WAIT0()   asm volatile("cp.async.wait_group 0;" ::: "memory")
#define CP_WAIT1()   asm volatile("cp.async.wait_group 1;" ::: "memory")

#define LDSM4(r, addr) \
    asm volatile("ldmatrix.sync.aligned.m8n8.x4.shared.b16 {%0,%1,%2,%3}, [%4];" \
        : "=r"((r)[0]), "=r"((r)[1]), "=r"((r)[2]), "=r"((r)[3]) : "r"(addr))
#define LDSM2(r, addr) \
    asm volatile("ldmatrix.sync.aligned.m8n8.x2.shared.b16 {%0,%1}, [%2];" \
        : "=r"((r)[0]), "=r"((r)[1]) : "r"(addr))
#define LDSM4T(r, addr) \
    asm volatile("ldmatrix.sync.aligned.m8n8.x4.trans.shared.b16 {%0,%1,%2,%3}, [%4];" \
        : "=r"((r)[0]), "=r"((r)[1]), "=r"((r)[2]), "=r"((r)[3]) : "r"(addr))

__device__ __forceinline__ void mma16816(float* c, const uint32_t* a, const uint32_t* b) {
    asm volatile(
        "mma.sync.aligned.m16n8k16.row.col.f32.f16.f16.f32 "
        "{%0,%1,%2,%3}, {%4,%5,%6,%7}, {%8,%9}, {%0,%1,%2,%3};"
        : "+f"(c[0]), "+f"(c[1]), "+f"(c[2]), "+f"(c[3])
        : "r"(a[0]), "r"(a[1]), "r"(a[2]), "r"(a[3]), "r"(b[0]), "r"(b[1]));
}

// ===========================================================================
// Single-plane HGEMM (known good): C = A[M,K] @ Bt[N,K]^T (+bias)(+relu).
// A selected per N-tile: bx < a2Start -> Ah, else A2. Output: fp32 C32 OR
// fp16 into up to 3 dest buffers (bx/dstTiles, ld outLd).
// Tile 128x128x64, 256 threads, 3-stage cp.async (96KB smem, 2 CTA/SM).
// ===========================================================================
#define HG1_STAGE 32768
#define HG1_SMEM  (3 * HG1_STAGE)

__global__ void __launch_bounds__(256, 2)
hgemm1_kernel(const __half* __restrict__ Ah, const __half* __restrict__ A2,
              int a2Start,
              const __half* __restrict__ Bt, const float* __restrict__ bias,
              float* __restrict__ C32,
              __half* __restrict__ D0, __half* __restrict__ D1, __half* __restrict__ D2,
              int dstTiles, int outLd, int N, int K, int relu)
{
    extern __shared__ char smem[];
    uint32_t sb = smem_u32(smem);
    int tid = threadIdx.x;
    int lane = tid & 31;
    int wid = tid >> 5;
    int wm = wid & 1, wn = wid >> 1;
    int bx = blockIdx.x, by = blockIdx.y;

    const __half* Abase = (bx < a2Start) ? Ah : A2;
    const __half* gA = Abase + (size_t)by * 128 * K;
    const __half* gB = Bt + (size_t)bx * 128 * K;

    int lrow = tid >> 3;
    int lch = tid & 7;
    uint32_t soff[4];
#pragma unroll
    for (int i = 0; i < 4; i++) {
        int r = lrow + 32 * i;
        soff[i] = (uint32_t)(r * 128 + ((lch ^ (r & 7)) * 16));
    }

    uint32_t aOff[4], aX[4], bOff[4], bX[4];
#pragma unroll
    for (int mf = 0; mf < 4; mf++) {
        int r = wm * 64 + mf * 16 + (lane & 15);
        aOff[mf] = r * 128; aX[mf] = r & 7;
    }
#pragma unroll
    for (int nf = 0; nf < 4; nf++) {
        int r = wn * 32 + nf * 8 + (lane & 7);
        bOff[nf] = r * 128; bX[nf] = r & 7;
    }
    int aSel = lane >> 4;
    int bSel = (lane >> 3) & 1;

    float acc[4][4][4];
#pragma unroll
    for (int mf = 0; mf < 4; mf++)
#pragma unroll
        for (int nf = 0; nf < 4; nf++)
#pragma unroll
            for (int r = 0; r < 4; r++) acc[mf][nf][r] = 0.f;

    const int KT = K >> 6;

#pragma unroll
    for (int p = 0; p < 2; p++) {
        uint32_t st = sb + p * HG1_STAGE;
        int k0 = p << 6;
#pragma unroll
        for (int i = 0; i < 4; i++) {
            int r = lrow + 32 * i;
            CP_ASYNC16(st + soff[i],         gA + (size_t)r * K + k0 + lch * 8);
            CP_ASYNC16(st + 16384 + soff[i], gB + (size_t)r * K + k0 + lch * 8);
        }
        CP_COMMIT();
    }

    int cur = 0, pf = 2;
    for (int kt = 0; kt < KT; kt++) {
        if (kt + 2 < KT) { CP_WAIT1(); } else { CP_WAIT0(); }
        __syncthreads();

        if (kt + 2 < KT) {
            uint32_t st = sb + pf * HG1_STAGE;
            int k0 = (kt + 2) << 6;
#pragma unroll
            for (int i = 0; i < 4; i++) {
                int r = lrow + 32 * i;
                CP_ASYNC16(st + soff[i],         gA + (size_t)r * K + k0 + lch * 8);
                CP_ASYNC16(st + 16384 + soff[i], gB + (size_t)r * K + k0 + lch * 8);
            }
            CP_COMMIT();
        }

        uint32_t aBase = sb + cur * HG1_STAGE;
        uint32_t bBase = aBase + 16384;

#pragma unroll
        for (int ks = 0; ks < 4; ks++) {
            int cA = ks * 2 + aSel;
            int cB = ks * 2 + bSel;
            uint32_t a[4][4], b[4][2];
#pragma unroll
            for (int mf = 0; mf < 4; mf++)
                LDSM4(a[mf], aBase + aOff[mf] + ((cA ^ aX[mf]) << 4));
#pragma unroll
            for (int nf = 0; nf < 4; nf++)
                LDSM2(b[nf], bBase + bOff[nf] + ((cB ^ bX[nf]) << 4));
#pragma unroll
            for (int mf = 0; mf < 4; mf++)
#pragma unroll
                for (int nf = 0; nf < 4; nf++)
                    mma16816(acc[mf][nf], a[mf], b[nf]);
        }

        cur = (cur == 2) ? 0 : cur + 1;
        pf  = (pf == 2) ? 0 : pf + 1;
    }

    int g = lane >> 2, tig = lane & 3;
    int which = bx / dstTiles;
    int lbx = bx - which * dstTiles;
    __half* D = (which == 0) ? D0 : ((which == 1) ? D1 : D2);
#pragma unroll
    for (int mf = 0; mf < 4; mf++) {
#pragma unroll
        for (int nf = 0; nf < 4; nf++) {
            int r0 = by * 128 + wm * 64 + mf * 16 + g;
            int cl = wn * 32 + nf * 8 + tig * 2;
            int cglob = bx * 128 + cl;
            float b0 = 0.f, b1 = 0.f;
            if (bias) { b0 = bias[cglob]; b1 = bias[cglob + 1]; }
            float v0 = acc[mf][nf][0] + b0, v1 = acc[mf][nf][1] + b1;
            float v2 = acc[mf][nf][2] + b0, v3 = acc[mf][nf][3] + b1;
            if (relu) {
                v0 = fmaxf(v0, 0.f); v1 = fmaxf(v1, 0.f);
                v2 = fmaxf(v2, 0.f); v3 = fmaxf(v3, 0.f);
            }
            if (C32) {
                *(float2*)(C32 + (size_t)r0 * N + cglob) = make_float2(v0, v1);
                *(float2*)(C32 + (size_t)(r0 + 8) * N + cglob) = make_float2(v2, v3);
            } else {
                int c = lbx * 128 + cl;
                *(__half2*)(D + (size_t)r0 * outLd + c) = __floats2half2_rn(v0, v1);
                *(__half2*)(D + (size_t)(r0 + 8) * outLd + c) = __floats2half2_rn(v2, v3);
            }
        }
    }
}

// ---------------------------------------------------------------------------
// Tensor-core flash attention (known good). grid (BATCH*NH, T/64), 128 thr.
// ---------------------------------------------------------------------------
__global__ void __launch_bounds__(128)
fa_mma_kernel(const __half* __restrict__ Qm, const __half* __restrict__ Km,
              const __half* __restrict__ Vm, __half* __restrict__ Oh, int causal)
{
    __shared__ __half sQ[64 * 64];
    __shared__ __half sK[2][64 * 64];
    __shared__ __half sV[2][64 * 64];

    int tid = threadIdx.x, lane = tid & 31, w = tid >> 5;
    int g = lane >> 2, tig = lane & 3;
    int bh = blockIdx.x, b = bh >> 4, h = bh & 15;
    int qt = blockIdx.y;

    uint32_t sq = smem_u32(sQ);
    uint32_t skb[2] = { smem_u32(sK[0]), smem_u32(sK[1]) };
    uint32_t svb[2] = { smem_u32(sV[0]), smem_u32(sV[1]) };

    const __half* Qg = Qm + ((size_t)(b * T + qt * 64)) * E + h * HS;
    const __half* K0 = Km + ((size_t)(b * T)) * E + h * HS;
    const __half* V0 = Vm + ((size_t)(b * T)) * E + h * HS;

#pragma unroll
    for (int i = 0; i < 4; i++) {
        int c = tid + i * 128; int r = c >> 3; int ch = c & 7;
        uint32_t off = r * 128 + ((ch ^ (r & 7)) << 4);
        CP_ASYNC16(sq + off, Qg + (size_t)r * E + ch * 8);
        CP_ASYNC16(skb[0] + off, K0 + (size_t)r * E + ch * 8);
        CP_ASYNC16(svb[0] + off, V0 + (size_t)r * E + ch * 8);
    }
    CP_COMMIT();
    CP_WAIT0();
    __syncthreads();

    uint32_t qf[4][4];
    {
        int r = w * 16 + (lane & 15); int sel = lane >> 4; int rx = r & 7;
        uint32_t ro = sq + r * 128;
#pragma unroll
        for (int ks = 0; ks < 4; ks++)
            LDSM4(qf[ks], ro + (((2 * ks + sel) ^ rx) << 4));
    }

    float oacc[8][4];
#pragma unroll
    for (int n = 0; n < 8; n++)
#pragma unroll
        for (int e = 0; e < 4; e++) oacc[n][e] = 0.f;
    float m0 = -1e30f, m1 = -1e30f, l0 = 0.f, l1 = 0.f;

    int nk = causal ? (qt + 1) : (T / 64);
    const float SC2 = ATT_SCALE * LOG2E;

    for (int kt = 0; kt < nk; kt++) {
        int cur = kt & 1;
        if (kt + 1 < nk) {
            int nst = cur ^ 1;
            const __half* Kg = Km + ((size_t)(b * T + (kt + 1) * 64)) * E + h * HS;
            const __half* Vg = Vm + ((size_t)(b * T + (kt + 1) * 64)) * E + h * HS;
#pragma unroll
            for (int i = 0; i < 4; i++) {
                int c = tid + i * 128; int r = c >> 3; int ch = c & 7;
                uint32_t off = r * 128 + ((ch ^ (r & 7)) << 4);
                CP_ASYNC16(skb[nst] + off, Kg + (size_t)r * E + ch * 8);
                CP_ASYNC16(svb[nst] + off, Vg + (size_t)r * E + ch * 8);
            }
            CP_COMMIT();
        }

        float sacc[8][4];
#pragma unroll
        for (int n = 0; n < 8; n++)
#pragma unroll
            for (int e = 0; e < 4; e++) sacc[n][e] = 0.f;

        uint32_t skc = skb[cur], svc = svb[cur];
#pragma unroll
        for (int ks = 0; ks < 4; ks++) {
            uint32_t kb[8][2];
            int rl = lane & 7, sel = (lane >> 3) & 1;
#pragma unroll
            for (int n = 0; n < 8; n++) {
                int rr = n * 8 + rl;
                LDSM2(kb[n], skc + rr * 128 + (((2 * ks + sel) ^ (rr & 7)) << 4));
            }
#pragma unroll
            for (int n = 0; n < 8; n++) mma16816(sacc[n], qf[ks], kb[n]);
        }

#pragma unroll
        for (int n = 0; n < 8; n++)
#pragma unroll
            for (int e = 0; e < 4; e++) sacc[n][e] *= SC2;
        if (causal && kt == qt) {
            int row0 = w * 16 + g;
#pragma unroll
            for (int n = 0; n < 8; n++) {
                int c0 = n * 8 + tig * 2;
                if (c0     > row0)     sacc[n][0] = -1e30f;
                if (c0 + 1 > row0)     sacc[n][1] = -1e30f;
                if (c0     > row0 + 8) sacc[n][2] = -1e30f;
                if (c0 + 1 > row0 + 8) sacc[n][3] = -1e30f;
            }
        }

        float mx0 = -1e30f, mx1 = -1e30f;
#pragma unroll
        for (int n = 0; n < 8; n++) {
            mx0 = fmaxf(mx0, fmaxf(sacc[n][0], sacc[n][1]));
            mx1 = fmaxf(mx1, fmaxf(sacc[n][2], sacc[n][3]));
        }
        mx0 = fmaxf(mx0, __shfl_xor_sync(0xffffffffu, mx0, 1));
        mx0 = fmaxf(mx0, __shfl_xor_sync(0xffffffffu, mx0, 2));
        mx1 = fmaxf(mx1, __shfl_xor_sync(0xffffffffu, mx1, 1));
        mx1 = fmaxf(mx1, __shfl_xor_sync(0xffffffffu, mx1, 2));
        float mn0 = fmaxf(m0, mx0), mn1 = fmaxf(m1, mx1);
        float a0 = exp2f(m0 - mn0), a1 = exp2f(m1 - mn1);
        m0 = mn0; m1 = mn1;

        float ps0 = 0.f, ps1 = 0.f;
        uint32_t pfr[4][4];
#pragma unroll
        for (int n = 0; n < 8; n++) {
            float p0 = exp2f(sacc[n][0] - mn0), p1 = exp2f(sacc[n][1] - mn0);
            float p2 = exp2f(sacc[n][2] - mn1), p3 = exp2f(sacc[n][3] - mn1);
            ps0 += p0 + p1; ps1 += p2 + p3;
            __half2 h01 = __floats2half2_rn(p0, p1);
            __half2 h23 = __floats2half2_rn(p2, p3);
            int ks = n >> 1, hi = (n & 1) * 2;
            pfr[ks][hi]     = *(uint32_t*)&h01;
            pfr[ks][hi + 1] = *(uint32_t*)&h23;
        }
        l0 = l0 * a0 + ps0;
        l1 = l1 * a1 + ps1;
#pragma unroll
        for (int n = 0; n < 8; n++) {
            oacc[n][0] *= a0; oacc[n][1] *= a0;
            oacc[n][2] *= a1; oacc[n][3] *= a1;
        }

        {
            int rl = lane & 15, cs = lane >> 4;
#pragma unroll
            for (int np = 0; np < 4; np++) {
#pragma unroll
                for (int ks = 0; ks < 4; ks++) {
                    uint32_t vb[4];
                    int rr = ks * 16 + rl;
                    int ch = np * 2 + cs;
                    LDSM4T(vb, svc + rr * 128 + ((ch ^ (rr & 7)) << 4));
                    mma16816(oacc[2 * np],     pfr[ks], vb);
                    mma16816(oacc[2 * np + 1], pfr[ks], vb + 2);
                }
            }
        }

        CP_WAIT0();
        __syncthreads();
    }

    l0 += __shfl_xor_sync(0xffffffffu, l0, 1);
    l0 += __shfl_xor_sync(0xffffffffu, l0, 2);
    l1 += __shfl_xor_sync(0xffffffffu, l1, 1);
    l1 += __shfl_xor_sync(0xffffffffu, l1, 2);
    float i0 = 1.f / l0, i1 = 1.f / l1;

    size_t base0 = ((size_t)(b * T + qt * 64 + w * 16 + g)) * E + h * HS;
    size_t base1 = base0 + (size_t)8 * E;
#pragma unroll
    for (int n = 0; n < 8; n++) {
        int c = n * 8 + tig * 2;
        *(__half2*)(Oh + base0 + c) = __floats2half2_rn(oacc[n][0] * i0, oacc[n][1] * i0);
        *(__half2*)(Oh + base1 + c) = __floats2half2_rn(oacc[n][2] * i1, oacc[n][3] * i1);
    }
}

// ---------------------------------------------------------------------------
// Fast batched weight transpose to fp16: 64x64 tiles, float4 loads.
// ---------------------------------------------------------------------------
struct TP8 { const float* s[8]; __half* d[8]; };

__global__ void __launch_bounds__(256)
transpose64_kernel(TP8 p)
{
    __shared__ float t[64][65];
    const float* in = p.s[blockIdx.z];
    __half* out = p.d[blockIdx.z];
    int bx = blockIdx.x * 64, by = blockIdx.y * 64;
    int tx = threadIdx.x & 15, ty = threadIdx.x >> 4;

#pragma unroll
    for (int j = 0; j < 4; j++) {
        int r = ty + j * 16;
        float4 v = *(const float4*)(in + (size_t)(by + r) * E + bx + tx * 4);
        t[tx * 4 + 0][r] = v.x;
        t[tx * 4 + 1][r] = v.y;
        t[tx * 4 + 2][r] = v.z;
        t[tx * 4 + 3][r] = v.w;
    }
    __syncthreads();
#pragma unroll
    for (int j = 0; j < 4; j++) {
        int c = ty + j * 16;
        __half2 h0 = __floats2half2_rn(t[c][tx * 4 + 0], t[c][tx * 4 + 1]);
        __half2 h1 = __floats2half2_rn(t[c][tx * 4 + 2], t[c][tx * 4 + 3]);
        *(__half2*)(out + (size_t)(bx + c) * E + by + tx * 4)     = h0;
        *(__half2*)(out + (size_t)(bx + c) * E + by + tx * 4 + 2) = h1;
    }
}

// FFN weight transposes, same 64x64 scheme.
__global__ void __launch_bounds__(256)
transpose_ff_kernel(const float* __restrict__ w1, __half* __restrict__ w1t,
                    const float* __restrict__ w2, __half* __restrict__ w2t)
{
    __shared__ float t[64][65];
    const float* in;  __half* out;  int R, C;
    if (blockIdx.z == 0) { in = w1; out = w1t; R = E;  C = HID; }
    else                 { in = w2; out = w2t; R = HID; C = E;  }
    int bx = blockIdx.x * 64, by = blockIdx.y * 64;
    if (bx >= C || by >= R) return;
    int tx = threadIdx.x & 15, ty = threadIdx.x >> 4;

#pragma unroll
    for (int j = 0; j < 4; j++) {
        int r = ty + j * 16;
        float4 v = *(const float4*)(in + (size_t)(by + r) * C + bx + tx * 4);
        t[tx * 4 + 0][r] = v.x;
        t[tx * 4 + 1][r] = v.y;
        t[tx * 4 + 2][r] = v.z;
        t[tx * 4 + 3][r] = v.w;
    }
    __syncthreads();
#pragma unroll
    for (int j = 0; j < 4; j++) {
        int c = ty + j * 16;
        __half2 h0 = __floats2half2_rn(t[c][tx * 4 + 0], t[c][tx * 4 + 1]);
        __half2 h1 = __floats2half2_rn(t[c][tx * 4 + 2], t[c][tx * 4 + 3]);
        *(__half2*)(out + (size_t)(bx + c) * R + by + tx * 4)     = h0;
        *(__half2*)(out + (size_t)(bx + c) * R + by + tx * 4 + 2) = h1;
    }
}

// ---------------------------------------------------------------------------
// Single fp32 -> fp16 convert, 4 float4s per thread
// ---------------------------------------------------------------------------
__global__ void __launch_bounds__(256)
conv1_h_kernel(const float* __restrict__ src, __half* __restrict__ dst, int n)
{
    int base = (blockIdx.x * 256 + threadIdx.x) * 4;
    int stride = gridDim.x * 256 * 4;
#pragma unroll
    for (int k = 0; k < 4; k++) {
        int i = base + k * stride;
        if (i < n) {
            float4 v = *(const float4*)(src + i);
            *(__half2*)(dst + i)     = __floats2half2_rn(v.x, v.y);
            *(__half2*)(dst + i + 2) = __floats2half2_rn(v.z, v.w);
        }
    }
}

// ---------------------------------------------------------------------------
// Fused residual + LayerNorm, fp16 residual input (+ optional fp16 plane)
// ---------------------------------------------------------------------------
__global__ void __launch_bounds__(256)
ln_residual_kernel(const float* __restrict__ X, const __half* __restrict__ R,
                   const float* __restrict__ G, const float* __restrict__ Bt,
                   float* __restrict__ Out, __half* __restrict__ Oh)
{
    const int N = E;
    int row = blockIdx.x;
    int tid = threadIdx.x;
    int lane = tid & 31, wid = tid >> 5;
    __shared__ float sm[8];
    __shared__ float stats[2];

    int idx = tid * 4;
    float4 xv = *(const float4*)(X + (size_t)row * N + idx);
    __half2 r01 = *(const __half2*)(R + (size_t)row * N + idx);
    __half2 r23 = *(const __half2*)(R + (size_t)row * N + idx + 2);
    float2 rf01 = __half22float2(r01);
    float2 rf23 = __half22float2(r23);
    float v0 = xv.x + rf01.x, v1 = xv.y + rf01.y;
    float v2 = xv.z + rf23.x, v3 = xv.w + rf23.y;

    float s = (v0 + v1) + (v2 + v3);
#pragma unroll
    for (int off = 16; off > 0; off >>= 1) s += __shfl_down_sync(0xffffffffu, s, off);
    if (lane == 0) sm[wid] = s;
    __syncthreads();
    if (tid == 0) {
        float t = 0.f;
#pragma unroll
        for (int i = 0; i < 8; i++) t += sm[i];
        stats[0] = t * (1.f / N);
    }
    __syncthreads();
    float mu = stats[0];

    float d0 = v0 - mu, d1 = v1 - mu, d2 = v2 - mu, d3 = v3 - mu;
    float vs = (d0 * d0 + d1 * d1) + (d2 * d2 + d3 * d3);
#pragma unroll
    for (int off = 16; off > 0; off >>= 1) vs += __shfl_down_sync(0xffffffffu, vs, off);
    __syncthreads();
    if (lane == 0) sm[wid] = vs;
    __syncthreads();
    if (tid == 0) {
        float t = 0.f;
#pragma unroll
        for (int i = 0; i < 8; i++) t += sm[i];
        stats[1] = rsqrtf(t * (1.f / N) + LN_EPS);
    }
    __syncthreads();
    float rstd = stats[1];

    float4 gv = *(const float4*)(G + idx);
    float4 bv = *(const float4*)(Bt + idx);
    float y0 = d0 * rstd * gv.x + bv.x;
    float y1 = d1 * rstd * gv.y + bv.y;
    float y2 = d2 * rstd * gv.z + bv.z;
    float y3 = d3 * rstd * gv.w + bv.w;
    *(float4*)(Out + (size_t)row * N + idx) = make_float4(y0, y1, y2, y3);
    if (Oh) {
        *(__half2*)(Oh + (size_t)row * N + idx)     = __floats2half2_rn(y0, y1);
        *(__half2*)(Oh + (size_t)row * N + idx + 2) = __floats2half2_rn(y2, y3);
    }
}

// ---------------------------------------------------------------------------
// Launch: side stream overlaps preprocessing AND the CA k/v projection.
// ---------------------------------------------------------------------------
extern "C" void kernel_launch(void* const* d_in, const int* in_sizes, int n_in,
                              void* d_out, int out_size)
{
    const float* x       = (const float*)d_in[0];
    const float* context = (const float*)d_in[1];
    const float* sa_wq = (const float*)d_in[2];
    const float* sa_wk = (const float*)d_in[3];
    const float* sa_wv = (const float*)d_in[4];
    const float* sa_wo = (const float*)d_in[5];
    const float* sa_bo = (const float*)d_in[6];
    const float* ca_wq = (const float*)d_in[7];
    const float* ca_wk = (const float*)d_in[8];
    const float* ca_wv = (const float*)d_in[9];
    const float* ca_wo = (const float*)d_in[10];
    const float* ca_bo = (const float*)d_in[11];
    const float* n1_g  = (const float*)d_in[12];
    const float* n1_b  = (const float*)d_in[13];
    const float* n2_g  = (const float*)d_in[14];
    const float* n2_b  = (const float*)d_in[15];
    const float* n3_g  = (const float*)d_in[16];
    const float* n3_b  = (const float*)d_in[17];
    const float* ff_w1 = (const float*)d_in[18];
    const float* ff_b1 = (const float*)d_in[19];
    const float* ff_w2 = (const float*)d_in[20];
    const float* ff_b2 = (const float*)d_in[21];
    float* out = (float*)d_out;

    float *x1f_, *x2f_;
    cudaGetSymbolAddress((void**)&x1f_, g_x1f);
    cudaGetSymbolAddress((void**)&x2f_, g_x2f);

    __half *tmph, *qh, *kh, *vh, *kh2, *vh2, *ath;
    cudaGetSymbolAddress((void**)&tmph, g_tmph);
    cudaGetSymbolAddress((void**)&qh,  g_qh);
    cudaGetSymbolAddress((void**)&kh,  g_kh);
    cudaGetSymbolAddress((void**)&vh,  g_vh);
    cudaGetSymbolAddress((void**)&kh2, g_kh2);
    cudaGetSymbolAddress((void**)&vh2, g_vh2);
    cudaGetSymbolAddress((void**)&ath, g_ath);

    __half *xh, *ctxh, *x1h, *x2h, *ffh;
    cudaGetSymbolAddress((void**)&xh,   g_xh);
    cudaGetSymbolAddress((void**)&ctxh, g_ctxh);
    cudaGetSymbolAddress((void**)&x1h,  g_x1h);
    cudaGetSymbolAddress((void**)&x2h,  g_x2h);
    cudaGetSymbolAddress((void**)&ffh,  g_ffh);

    __half *wqkv, *wqkvca, *wot, *cwot, *w1t, *w2t;
    cudaGetSymbolAddress((void**)&wqkv,   g_wqkv_sa);
    cudaGetSymbolAddress((void**)&wqkvca, g_wqkv_ca);
    cudaGetSymbolAddress((void**)&wot,    g_sa_wot);
    cudaGetSymbolAddress((void**)&cwot,   g_ca_wot);
    cudaGetSymbolAddress((void**)&w1t,    g_w1t);
    cudaGetSymbolAddress((void**)&w2t,    g_w2t);

    cudaFuncSetAttribute(hgemm1_kernel,
                         cudaFuncAttributeMaxDynamicSharedMemorySize, HG1_SMEM);

    cudaStream_t s2;
    cudaStreamCreateWithFlags(&s2, cudaStreamNonBlocking);
    cudaEvent_t evF, evJ, evKV;
    cudaEventCreateWithFlags(&evF,  cudaEventDisableTiming);
    cudaEventCreateWithFlags(&evJ,  cudaEventDisableTiming);
    cudaEventCreateWithFlags(&evKV, cudaEventDisableTiming);

    int nElem = M_ROWS * E;

    dim3 gQKV(3 * E / 128, M_ROWS / 128);   // 24 x 32
    dim3 gKV(2 * E / 128, M_ROWS / 128);    // 16 x 32
    dim3 gE(E / 128, M_ROWS / 128);         // 8 x 32
    dim3 gH(HID / 128, M_ROWS / 128);       // 32 x 32
    dim3 gFA(BATCH * NH, T / 64);

    // Fork: side stream does off-critical preprocessing, then the CA k/v GEMM.
    cudaEventRecord(evF, 0);
    cudaStreamWaitEvent(s2, evF, 0);
    {
        TP8 side;
        side.s[0] = sa_wo; side.d[0] = wot;
        side.s[1] = ca_wq; side.d[1] = wqkvca;
        side.s[2] = ca_wk; side.d[2] = wqkvca + E * E;
        side.s[3] = ca_wv; side.d[3] = wqkvca + 2 * E * E;
        side.s[4] = ca_wo; side.d[4] = cwot;
        transpose64_kernel<<<dim3(E / 64, E / 64, 5), 256, 0, s2>>>(side);
        transpose_ff_kernel<<<dim3(HID / 64, HID / 64, 2), 256, 0, s2>>>(ff_w1, w1t, ff_w2, w2t);
        conv1_h_kernel<<<nElem / 4096, 256, 0, s2>>>(context, ctxh, nElem);
        cudaEventRecord(evJ, s2);
        // CA k/v projection overlaps SA QKV GEMM / FA / wo / LN1 on main.
        hgemm1_kernel<<<gKV, 256, HG1_SMEM, s2>>>(
            ctxh, nullptr, 1 << 30, wqkvca + E * E, nullptr, nullptr,
            kh2, vh2, nullptr, 8, E, 2 * E, E, 0);
        cudaEventRecord(evKV, s2);
    }

    // Main (critical) path: SA q/k/v weights + x convert only.
    {
        TP8 mainp;
        mainp.s[0] = sa_wq; mainp.d[0] = wqkv;
        mainp.s[1] = sa_wk; mainp.d[1] = wqkv + E * E;
        mainp.s[2] = sa_wv; mainp.d[2] = wqkv + 2 * E * E;
        transpose64_kernel<<<dim3(E / 64, E / 64, 3), 256>>>(mainp);
        conv1_h_kernel<<<nElem / 4096, 256>>>(x, xh, nElem);
    }

    // ---- Self-attention ----
    hgemm1_kernel<<<gQKV, 256, HG1_SMEM>>>(xh, nullptr, 1 << 30, wqkv, nullptr, nullptr,
                                           qh, kh, vh, 8, E, 3 * E, E, 0);
    fa_mma_kernel<<<gFA, 128>>>(qh, kh, vh, ath, 1);

    // Join 1: wot ready (side-stream preprocessing done).
    cudaStreamWaitEvent(0, evJ, 0);

    hgemm1_kernel<<<gE, 256, HG1_SMEM>>>(ath, nullptr, 1 << 30, wot, sa_bo, nullptr,
                                         tmph, nullptr, nullptr, 8, E, E, E, 0);
    ln_residual_kernel<<<M_ROWS, 256>>>(x, tmph, n1_g, n1_b, x1f_, x1h);

    // ---- Cross-attention: q projection only (k/v done on side stream) ----
    hgemm1_kernel<<<gE, 256, HG1_SMEM>>>(x1h, nullptr, 1 << 30, wqkvca, nullptr, nullptr,
                                         qh, nullptr, nullptr, 8, E, E, E, 0);

    // Join 2: CA k/v ready.
    cudaStreamWaitEvent(0, evKV, 0);

    fa_mma_kernel<<<gFA, 128>>>(qh, kh2, vh2, ath, 0);
    hgemm1_kernel<<<gE, 256, HG1_SMEM>>>(ath, nullptr, 1 << 30, cwot, ca_bo, nullptr,
                                         tmph, nullptr, nullptr, 8, E, E, E, 0);
    ln_residual_kernel<<<M_ROWS, 256>>>(x1f_, tmph, n2_g, n2_b, x2f_, x2h);

    // ---- FFN ----
    hgemm1_kernel<<<gH, 256, HG1_SMEM>>>(x2h, nullptr, 1 << 30, w1t, ff_b1, nullptr,
                                         ffh, nullptr, nullptr, 32, HID, HID, E, 1);
    hgemm1_kernel<<<gE, 256, HG1_SMEM>>>(ffh, nullptr, 1 << 30, w2t, ff_b2, nullptr,
                                         tmph, nullptr, nullptr, 8, E, E, HID, 0);
    ln_residual_kernel<<<M_ROWS, 256>>>(x2f_, tmph, n3_g, n3_b, out, nullptr);

    cudaEventDestroy(evF);
    cudaEventDestroy(evJ);
    cudaEventDestroy(evKV);
    cudaStreamDestroy(s2);
}

// round 16
// speedup vs baseline: 1.1423x; 1.0260x over previous
#include <cuda_runtime.h>
#include <cuda_fp16.h>
#include <math.h>
#include <stdint.h>

// Problem constants
#define BATCH 4
#define T 1024
#define E 1024
#define NH 16
#define HS 64
#define HID 4096
#define M_ROWS (BATCH * T)   // 4096
#define LN_EPS 1e-5f
#define ATT_SCALE 0.03125f   // E^-0.25 on q and k each -> E^-0.5 on dot
#define LOG2E 1.4426950408889634f

// ---------------------------------------------------------------------------
// Scratch (__device__ globals; no allocation allowed)
// ---------------------------------------------------------------------------
__device__ __half g_tmph[M_ROWS * E];
__device__ __half g_qh[M_ROWS * E], g_kh[M_ROWS * E], g_vh[M_ROWS * E];
__device__ __half g_kh2[M_ROWS * E], g_vh2[M_ROWS * E];   // CA k/v (side stream)
__device__ __half g_ath[M_ROWS * E];
__device__ __half g_xh[M_ROWS * E];
__device__ __half g_ctxh[M_ROWS * E];
__device__ __half g_x1h[M_ROWS * E];       // LN1 out (fp16: GEMM A + residual)
__device__ __half g_x2h[M_ROWS * E];       // LN2 out
__device__ __half g_ffh[M_ROWS * HID];
// fp16 transposed weights [N,K] (QKV packed for fused projections)
__device__ __half g_wqkv_sa[3 * E * E];         // wq^T | wk^T | wv^T
__device__ __half g_wqkv_ca[3 * E * E];         // wq^T | wk^T | wv^T
__device__ __half g_sa_wot[E * E], g_ca_wot[E * E];
__device__ __half g_w1t[HID * E], g_w2t[E * HID];

// ---------------------------------------------------------------------------
// PTX helpers (sm_80+-compatible: cp.async, ldmatrix, mma.sync)
// ---------------------------------------------------------------------------
__device__ __forceinline__ uint32_t smem_u32(const void* p) {
    uint32_t a;
    asm("{ .reg .u64 t; cvta.to.shared.u64 t, %1; cvt.u32.u64 %0, t; }"
        : "=r"(a) : "l"(p));
    return a;
}

#define CP_ASYNC16(saddr, gptr) \
    asm volatile("cp.async.cg.shared.global [%0], [%1], 16;" \
        :: "r"(saddr), "l"(gptr) : "memory")
#define CP_COMMIT()  asm volatile("cp.async.commit_group;" ::: "memory")
#define CP_WAIT0()   asm volatile("cp.async.wait_group 0;" ::: "memory")
#define CP_WAIT1()   asm volatile("cp.async.wait_group 1;" ::: "memory")

#define LDSM4(r, addr) \
    asm volatile("ldmatrix.sync.aligned.m8n8.x4.shared.b16 {%0,%1,%2,%3}, [%4];" \
        : "=r"((r)[0]), "=r"((r)[1]), "=r"((r)[2]), "=r"((r)[3]) : "r"(addr))
#define LDSM2(r, addr) \
    asm volatile("ldmatrix.sync.aligned.m8n8.x2.shared.b16 {%0,%1}, [%2];" \
        : "=r"((r)[0]), "=r"((r)[1]) : "r"(addr))
#define LDSM4T(r, addr) \
    asm volatile("ldmatrix.sync.aligned.m8n8.x4.trans.shared.b16 {%0,%1,%2,%3}, [%4];" \
        : "=r"((r)[0]), "=r"((r)[1]), "=r"((r)[2]), "=r"((r)[3]) : "r"(addr))

__device__ __forceinline__ void mma16816(float* c, const uint32_t* a, const uint32_t* b) {
    asm volatile(
        "mma.sync.aligned.m16n8k16.row.col.f32.f16.f16.f32 "
        "{%0,%1,%2,%3}, {%4,%5,%6,%7}, {%8,%9}, {%0,%1,%2,%3};"
        : "+f"(c[0]), "+f"(c[1]), "+f"(c[2]), "+f"(c[3])
        : "r"(a[0]), "r"(a[1]), "r"(a[2]), "r"(a[3]), "r"(b[0]), "r"(b[1]));
}

// ===========================================================================
// Single-plane HGEMM (known good): C = A[M,K] @ Bt[N,K]^T (+bias)(+relu).
// A selected per N-tile: bx < a2Start -> Ah, else A2. Output: fp32 C32 OR
// fp16 into up to 3 dest buffers (bx/dstTiles, ld outLd).
// Tile 128x128x64, 256 threads, 3-stage cp.async (96KB smem, 2 CTA/SM).
// ===========================================================================
#define HG1_STAGE 32768
#define HG1_SMEM  (3 * HG1_STAGE)

__global__ void __launch_bounds__(256, 2)
hgemm1_kernel(const __half* __restrict__ Ah, const __half* __restrict__ A2,
              int a2Start,
              const __half* __restrict__ Bt, const float* __restrict__ bias,
              float* __restrict__ C32,
              __half* __restrict__ D0, __half* __restrict__ D1, __half* __restrict__ D2,
              int dstTiles, int outLd, int N, int K, int relu)
{
    extern __shared__ char smem[];
    uint32_t sb = smem_u32(smem);
    int tid = threadIdx.x;
    int lane = tid & 31;
    int wid = tid >> 5;
    int wm = wid & 1, wn = wid >> 1;
    int bx = blockIdx.x, by = blockIdx.y;

    const __half* Abase = (bx < a2Start) ? Ah : A2;
    const __half* gA = Abase + (size_t)by * 128 * K;
    const __half* gB = Bt + (size_t)bx * 128 * K;

    int lrow = tid >> 3;
    int lch = tid & 7;
    uint32_t soff[4];
#pragma unroll
    for (int i = 0; i < 4; i++) {
        int r = lrow + 32 * i;
        soff[i] = (uint32_t)(r * 128 + ((lch ^ (r & 7)) * 16));
    }

    uint32_t aOff[4], aX[4], bOff[4], bX[4];
#pragma unroll
    for (int mf = 0; mf < 4; mf++) {
        int r = wm * 64 + mf * 16 + (lane & 15);
        aOff[mf] = r * 128; aX[mf] = r & 7;
    }
#pragma unroll
    for (int nf = 0; nf < 4; nf++) {
        int r = wn * 32 + nf * 8 + (lane & 7);
        bOff[nf] = r * 128; bX[nf] = r & 7;
    }
    int aSel = lane >> 4;
    int bSel = (lane >> 3) & 1;

    float acc[4][4][4];
#pragma unroll
    for (int mf = 0; mf < 4; mf++)
#pragma unroll
        for (int nf = 0; nf < 4; nf++)
#pragma unroll
            for (int r = 0; r < 4; r++) acc[mf][nf][r] = 0.f;

    const int KT = K >> 6;

#pragma unroll
    for (int p = 0; p < 2; p++) {
        uint32_t st = sb + p * HG1_STAGE;
        int k0 = p << 6;
#pragma unroll
        for (int i = 0; i < 4; i++) {
            int r = lrow + 32 * i;
            CP_ASYNC16(st + soff[i],         gA + (size_t)r * K + k0 + lch * 8);
            CP_ASYNC16(st + 16384 + soff[i], gB + (size_t)r * K + k0 + lch * 8);
        }
        CP_COMMIT();
    }

    int cur = 0, pf = 2;
    for (int kt = 0; kt < KT; kt++) {
        if (kt + 2 < KT) { CP_WAIT1(); } else { CP_WAIT0(); }
        __syncthreads();

        if (kt + 2 < KT) {
            uint32_t st = sb + pf * HG1_STAGE;
            int k0 = (kt + 2) << 6;
#pragma unroll
            for (int i = 0; i < 4; i++) {
                int r = lrow + 32 * i;
                CP_ASYNC16(st + soff[i],         gA + (size_t)r * K + k0 + lch * 8);
                CP_ASYNC16(st + 16384 + soff[i], gB + (size_t)r * K + k0 + lch * 8);
            }
            CP_COMMIT();
        }

        uint32_t aBase = sb + cur * HG1_STAGE;
        uint32_t bBase = aBase + 16384;

#pragma unroll
        for (int ks = 0; ks < 4; ks++) {
            int cA = ks * 2 + aSel;
            int cB = ks * 2 + bSel;
            uint32_t a[4][4], b[4][2];
#pragma unroll
            for (int mf = 0; mf < 4; mf++)
                LDSM4(a[mf], aBase + aOff[mf] + ((cA ^ aX[mf]) << 4));
#pragma unroll
            for (int nf = 0; nf < 4; nf++)
                LDSM2(b[nf], bBase + bOff[nf] + ((cB ^ bX[nf]) << 4));
#pragma unroll
            for (int mf = 0; mf < 4; mf++)
#pragma unroll
                for (int nf = 0; nf < 4; nf++)
                    mma16816(acc[mf][nf], a[mf], b[nf]);
        }

        cur = (cur == 2) ? 0 : cur + 1;
        pf  = (pf == 2) ? 0 : pf + 1;
    }

    int g = lane >> 2, tig = lane & 3;
    int which = bx / dstTiles;
    int lbx = bx - which * dstTiles;
    __half* D = (which == 0) ? D0 : ((which == 1) ? D1 : D2);
#pragma unroll
    for (int mf = 0; mf < 4; mf++) {
#pragma unroll
        for (int nf = 0; nf < 4; nf++) {
            int r0 = by * 128 + wm * 64 + mf * 16 + g;
            int cl = wn * 32 + nf * 8 + tig * 2;
            int cglob = bx * 128 + cl;
            float b0 = 0.f, b1 = 0.f;
            if (bias) { b0 = bias[cglob]; b1 = bias[cglob + 1]; }
            float v0 = acc[mf][nf][0] + b0, v1 = acc[mf][nf][1] + b1;
            float v2 = acc[mf][nf][2] + b0, v3 = acc[mf][nf][3] + b1;
            if (relu) {
                v0 = fmaxf(v0, 0.f); v1 = fmaxf(v1, 0.f);
                v2 = fmaxf(v2, 0.f); v3 = fmaxf(v3, 0.f);
            }
            if (C32) {
                *(float2*)(C32 + (size_t)r0 * N + cglob) = make_float2(v0, v1);
                *(float2*)(C32 + (size_t)(r0 + 8) * N + cglob) = make_float2(v2, v3);
            } else {
                int c = lbx * 128 + cl;
                *(__half2*)(D + (size_t)r0 * outLd + c) = __floats2half2_rn(v0, v1);
                *(__half2*)(D + (size_t)(r0 + 8) * outLd + c) = __floats2half2_rn(v2, v3);
            }
        }
    }
}

// ---------------------------------------------------------------------------
// Tensor-core flash attention (known good, + longest-job-first causal order).
// grid (BATCH*NH, T/64), 128 threads.
// ---------------------------------------------------------------------------
__global__ void __launch_bounds__(128)
fa_mma_kernel(const __half* __restrict__ Qm, const __half* __restrict__ Km,
              const __half* __restrict__ Vm, __half* __restrict__ Oh, int causal)
{
    __shared__ __half sQ[64 * 64];
    __shared__ __half sK[2][64 * 64];
    __shared__ __half sV[2][64 * 64];

    int tid = threadIdx.x, lane = tid & 31, w = tid >> 5;
    int g = lane >> 2, tig = lane & 3;
    int bh = blockIdx.x, b = bh >> 4, h = bh & 15;
    // Longest-job-first for causal: heavy q-tiles scheduled first.
    int qt = causal ? (gridDim.y - 1 - blockIdx.y) : blockIdx.y;

    uint32_t sq = smem_u32(sQ);
    uint32_t skb[2] = { smem_u32(sK[0]), smem_u32(sK[1]) };
    uint32_t svb[2] = { smem_u32(sV[0]), smem_u32(sV[1]) };

    const __half* Qg = Qm + ((size_t)(b * T + qt * 64)) * E + h * HS;
    const __half* K0 = Km + ((size_t)(b * T)) * E + h * HS;
    const __half* V0 = Vm + ((size_t)(b * T)) * E + h * HS;

#pragma unroll
    for (int i = 0; i < 4; i++) {
        int c = tid + i * 128; int r = c >> 3; int ch = c & 7;
        uint32_t off = r * 128 + ((ch ^ (r & 7)) << 4);
        CP_ASYNC16(sq + off, Qg + (size_t)r * E + ch * 8);
        CP_ASYNC16(skb[0] + off, K0 + (size_t)r * E + ch * 8);
        CP_ASYNC16(svb[0] + off, V0 + (size_t)r * E + ch * 8);
    }
    CP_COMMIT();
    CP_WAIT0();
    __syncthreads();

    uint32_t qf[4][4];
    {
        int r = w * 16 + (lane & 15); int sel = lane >> 4; int rx = r & 7;
        uint32_t ro = sq + r * 128;
#pragma unroll
        for (int ks = 0; ks < 4; ks++)
            LDSM4(qf[ks], ro + (((2 * ks + sel) ^ rx) << 4));
    }

    float oacc[8][4];
#pragma unroll
    for (int n = 0; n < 8; n++)
#pragma unroll
        for (int e = 0; e < 4; e++) oacc[n][e] = 0.f;
    float m0 = -1e30f, m1 = -1e30f, l0 = 0.f, l1 = 0.f;

    int nk = causal ? (qt + 1) : (T / 64);
    const float SC2 = ATT_SCALE * LOG2E;

    for (int kt = 0; kt < nk; kt++) {
        int cur = kt & 1;
        if (kt + 1 < nk) {
            int nst = cur ^ 1;
            const __half* Kg = Km + ((size_t)(b * T + (kt + 1) * 64)) * E + h * HS;
            const __half* Vg = Vm + ((size_t)(b * T + (kt + 1) * 64)) * E + h * HS;
#pragma unroll
            for (int i = 0; i < 4; i++) {
                int c = tid + i * 128; int r = c >> 3; int ch = c & 7;
                uint32_t off = r * 128 + ((ch ^ (r & 7)) << 4);
                CP_ASYNC16(skb[nst] + off, Kg + (size_t)r * E + ch * 8);
                CP_ASYNC16(svb[nst] + off, Vg + (size_t)r * E + ch * 8);
            }
            CP_COMMIT();
        }

        float sacc[8][4];
#pragma unroll
        for (int n = 0; n < 8; n++)
#pragma unroll
            for (int e = 0; e < 4; e++) sacc[n][e] = 0.f;

        uint32_t skc = skb[cur], svc = svb[cur];
#pragma unroll
        for (int ks = 0; ks < 4; ks++) {
            uint32_t kb[8][2];
            int rl = lane & 7, sel = (lane >> 3) & 1;
#pragma unroll
            for (int n = 0; n < 8; n++) {
                int rr = n * 8 + rl;
                LDSM2(kb[n], skc + rr * 128 + (((2 * ks + sel) ^ (rr & 7)) << 4));
            }
#pragma unroll
            for (int n = 0; n < 8; n++) mma16816(sacc[n], qf[ks], kb[n]);
        }

#pragma unroll
        for (int n = 0; n < 8; n++)
#pragma unroll
            for (int e = 0; e < 4; e++) sacc[n][e] *= SC2;
        if (causal && kt == qt) {
            int row0 = w * 16 + g;
#pragma unroll
            for (int n = 0; n < 8; n++) {
                int c0 = n * 8 + tig * 2;
                if (c0     > row0)     sacc[n][0] = -1e30f;
                if (c0 + 1 > row0)     sacc[n][1] = -1e30f;
                if (c0     > row0 + 8) sacc[n][2] = -1e30f;
                if (c0 + 1 > row0 + 8) sacc[n][3] = -1e30f;
            }
        }

        float mx0 = -1e30f, mx1 = -1e30f;
#pragma unroll
        for (int n = 0; n < 8; n++) {
            mx0 = fmaxf(mx0, fmaxf(sacc[n][0], sacc[n][1]));
            mx1 = fmaxf(mx1, fmaxf(sacc[n][2], sacc[n][3]));
        }
        mx0 = fmaxf(mx0, __shfl_xor_sync(0xffffffffu, mx0, 1));
        mx0 = fmaxf(mx0, __shfl_xor_sync(0xffffffffu, mx0, 2));
        mx1 = fmaxf(mx1, __shfl_xor_sync(0xffffffffu, mx1, 1));
        mx1 = fmaxf(mx1, __shfl_xor_sync(0xffffffffu, mx1, 2));
        float mn0 = fmaxf(m0, mx0), mn1 = fmaxf(m1, mx1);
        float a0 = exp2f(m0 - mn0), a1 = exp2f(m1 - mn1);
        m0 = mn0; m1 = mn1;

        float ps0 = 0.f, ps1 = 0.f;
        uint32_t pfr[4][4];
#pragma unroll
        for (int n = 0; n < 8; n++) {
            float p0 = exp2f(sacc[n][0] - mn0), p1 = exp2f(sacc[n][1] - mn0);
            float p2 = exp2f(sacc[n][2] - mn1), p3 = exp2f(sacc[n][3] - mn1);
            ps0 += p0 + p1; ps1 += p2 + p3;
            __half2 h01 = __floats2half2_rn(p0, p1);
            __half2 h23 = __floats2half2_rn(p2, p3);
            int ks = n >> 1, hi = (n & 1) * 2;
            pfr[ks][hi]     = *(uint32_t*)&h01;
            pfr[ks][hi + 1] = *(uint32_t*)&h23;
        }
        l0 = l0 * a0 + ps0;
        l1 = l1 * a1 + ps1;
#pragma unroll
        for (int n = 0; n < 8; n++) {
            oacc[n][0] *= a0; oacc[n][1] *= a0;
            oacc[n][2] *= a1; oacc[n][3] *= a1;
        }

        {
            int rl = lane & 15, cs = lane >> 4;
#pragma unroll
            for (int np = 0; np < 4; np++) {
#pragma unroll
                for (int ks = 0; ks < 4; ks++) {
                    uint32_t vb[4];
                    int rr = ks * 16 + rl;
                    int ch = np * 2 + cs;
                    LDSM4T(vb, svc + rr * 128 + ((ch ^ (rr & 7)) << 4));
                    mma16816(oacc[2 * np],     pfr[ks], vb);
                    mma16816(oacc[2 * np + 1], pfr[ks], vb + 2);
                }
            }
        }

        CP_WAIT0();
        __syncthreads();
    }

    l0 += __shfl_xor_sync(0xffffffffu, l0, 1);
    l0 += __shfl_xor_sync(0xffffffffu, l0, 2);
    l1 += __shfl_xor_sync(0xffffffffu, l1, 1);
    l1 += __shfl_xor_sync(0xffffffffu, l1, 2);
    float i0 = 1.f / l0, i1 = 1.f / l1;

    size_t base0 = ((size_t)(b * T + qt * 64 + w * 16 + g)) * E + h * HS;
    size_t base1 = base0 + (size_t)8 * E;
#pragma unroll
    for (int n = 0; n < 8; n++) {
        int c = n * 8 + tig * 2;
        *(__half2*)(Oh + base0 + c) = __floats2half2_rn(oacc[n][0] * i0, oacc[n][1] * i0);
        *(__half2*)(Oh + base1 + c) = __floats2half2_rn(oacc[n][2] * i1, oacc[n][3] * i1);
    }
}

// ---------------------------------------------------------------------------
// Fast batched weight transpose to fp16: 64x64 tiles, float4 loads.
// ---------------------------------------------------------------------------
struct TP8 { const float* s[8]; __half* d[8]; };

__global__ void __launch_bounds__(256)
transpose64_kernel(TP8 p)
{
    __shared__ float t[64][65];
    const float* in = p.s[blockIdx.z];
    __half* out = p.d[blockIdx.z];
    int bx = blockIdx.x * 64, by = blockIdx.y * 64;
    int tx = threadIdx.x & 15, ty = threadIdx.x >> 4;

#pragma unroll
    for (int j = 0; j < 4; j++) {
        int r = ty + j * 16;
        float4 v = *(const float4*)(in + (size_t)(by + r) * E + bx + tx * 4);
        t[tx * 4 + 0][r] = v.x;
        t[tx * 4 + 1][r] = v.y;
        t[tx * 4 + 2][r] = v.z;
        t[tx * 4 + 3][r] = v.w;
    }
    __syncthreads();
#pragma unroll
    for (int j = 0; j < 4; j++) {
        int c = ty + j * 16;
        __half2 h0 = __floats2half2_rn(t[c][tx * 4 + 0], t[c][tx * 4 + 1]);
        __half2 h1 = __floats2half2_rn(t[c][tx * 4 + 2], t[c][tx * 4 + 3]);
        *(__half2*)(out + (size_t)(bx + c) * E + by + tx * 4)     = h0;
        *(__half2*)(out + (size_t)(bx + c) * E + by + tx * 4 + 2) = h1;
    }
}

// FFN weight transposes, same 64x64 scheme.
__global__ void __launch_bounds__(256)
transpose_ff_kernel(const float* __restrict__ w1, __half* __restrict__ w1t,
                    const float* __restrict__ w2, __half* __restrict__ w2t)
{
    __shared__ float t[64][65];
    const float* in;  __half* out;  int R, C;
    if (blockIdx.z == 0) { in = w1; out = w1t; R = E;  C = HID; }
    else                 { in = w2; out = w2t; R = HID; C = E;  }
    int bx = blockIdx.x * 64, by = blockIdx.y * 64;
    if (bx >= C || by >= R) return;
    int tx = threadIdx.x & 15, ty = threadIdx.x >> 4;

#pragma unroll
    for (int j = 0; j < 4; j++) {
        int r = ty + j * 16;
        float4 v = *(const float4*)(in + (size_t)(by + r) * C + bx + tx * 4);
        t[tx * 4 + 0][r] = v.x;
        t[tx * 4 + 1][r] = v.y;
        t[tx * 4 + 2][r] = v.z;
        t[tx * 4 + 3][r] = v.w;
    }
    __syncthreads();
#pragma unroll
    for (int j = 0; j < 4; j++) {
        int c = ty + j * 16;
        __half2 h0 = __floats2half2_rn(t[c][tx * 4 + 0], t[c][tx * 4 + 1]);
        __half2 h1 = __floats2half2_rn(t[c][tx * 4 + 2], t[c][tx * 4 + 3]);
        *(__half2*)(out + (size_t)(bx + c) * R + by + tx * 4)     = h0;
        *(__half2*)(out + (size_t)(bx + c) * R + by + tx * 4 + 2) = h1;
    }
}

// ---------------------------------------------------------------------------
// Single fp32 -> fp16 convert, 4 float4s per thread
// ---------------------------------------------------------------------------
__global__ void __launch_bounds__(256)
conv1_h_kernel(const float* __restrict__ src, __half* __restrict__ dst, int n)
{
    int base = (blockIdx.x * 256 + threadIdx.x) * 4;
    int stride = gridDim.x * 256 * 4;
#pragma unroll
    for (int k = 0; k < 4; k++) {
        int i = base + k * stride;
        if (i < n) {
            float4 v = *(const float4*)(src + i);
            *(__half2*)(dst + i)     = __floats2half2_rn(v.x, v.y);
            *(__half2*)(dst + i + 2) = __floats2half2_rn(v.z, v.w);
        }
    }
}

// ---------------------------------------------------------------------------
// Fused residual + LayerNorm. X input: fp32 (Xf) OR fp16 (Xh16), exactly one
// non-null. R fp16. Output: fp32 (OutF) OR fp16 (OutH), exactly one non-null.
// The fp16 output serves as both GEMM A and next-LN residual.
// ---------------------------------------------------------------------------
__global__ void __launch_bounds__(256)
ln_residual_kernel(const float* __restrict__ Xf, const __half* __restrict__ Xh16,
                   const __half* __restrict__ R,
                   const float* __restrict__ G, const float* __restrict__ Bt,
                   float* __restrict__ OutF, __half* __restrict__ OutH)
{
    const int N = E;
    int row = blockIdx.x;
    int tid = threadIdx.x;
    int lane = tid & 31, wid = tid >> 5;
    __shared__ float sm[8];
    __shared__ float stats[2];

    int idx = tid * 4;
    float x0, x1, x2, x3;
    if (Xf) {
        float4 xv = *(const float4*)(Xf + (size_t)row * N + idx);
        x0 = xv.x; x1 = xv.y; x2 = xv.z; x3 = xv.w;
    } else {
        __half2 a01 = *(const __half2*)(Xh16 + (size_t)row * N + idx);
        __half2 a23 = *(const __half2*)(Xh16 + (size_t)row * N + idx + 2);
        float2 f01 = __half22float2(a01);
        float2 f23 = __half22float2(a23);
        x0 = f01.x; x1 = f01.y; x2 = f23.x; x3 = f23.y;
    }
    __half2 r01 = *(const __half2*)(R + (size_t)row * N + idx);
    __half2 r23 = *(const __half2*)(R + (size_t)row * N + idx + 2);
    float2 rf01 = __half22float2(r01);
    float2 rf23 = __half22float2(r23);
    float v0 = x0 + rf01.x, v1 = x1 + rf01.y;
    float v2 = x2 + rf23.x, v3 = x3 + rf23.y;

    float s = (v0 + v1) + (v2 + v3);
#pragma unroll
    for (int off = 16; off > 0; off >>= 1) s += __shfl_down_sync(0xffffffffu, s, off);
    if (lane == 0) sm[wid] = s;
    __syncthreads();
    if (tid == 0) {
        float t = 0.f;
#pragma unroll
        for (int i = 0; i < 8; i++) t += sm[i];
        stats[0] = t * (1.f / N);
    }
    __syncthreads();
    float mu = stats[0];

    float d0 = v0 - mu, d1 = v1 - mu, d2 = v2 - mu, d3 = v3 - mu;
    float vs = (d0 * d0 + d1 * d1) + (d2 * d2 + d3 * d3);
#pragma unroll
    for (int off = 16; off > 0; off >>= 1) vs += __shfl_down_sync(0xffffffffu, vs, off);
    __syncthreads();
    if (lane == 0) sm[wid] = vs;
    __syncthreads();
    if (tid == 0) {
        float t = 0.f;
#pragma unroll
        for (int i = 0; i < 8; i++) t += sm[i];
        stats[1] = rsqrtf(t * (1.f / N) + LN_EPS);
    }
    __syncthreads();
    float rstd = stats[1];

    float4 gv = *(const float4*)(G + idx);
    float4 bv = *(const float4*)(Bt + idx);
    float y0 = d0 * rstd * gv.x + bv.x;
    float y1 = d1 * rstd * gv.y + bv.y;
    float y2 = d2 * rstd * gv.z + bv.z;
    float y3 = d3 * rstd * gv.w + bv.w;
    if (OutF) {
        *(float4*)(OutF + (size_t)row * N + idx) = make_float4(y0, y1, y2, y3);
    } else {
        *(__half2*)(OutH + (size_t)row * N + idx)     = __floats2half2_rn(y0, y1);
        *(__half2*)(OutH + (size_t)row * N + idx + 2) = __floats2half2_rn(y2, y3);
    }
}

// ---------------------------------------------------------------------------
// Launch: side stream overlaps preprocessing AND the CA k/v projection.
// ---------------------------------------------------------------------------
extern "C" void kernel_launch(void* const* d_in, const int* in_sizes, int n_in,
                              void* d_out, int out_size)
{
    const float* x       = (const float*)d_in[0];
    const float* context = (const float*)d_in[1];
    const float* sa_wq = (const float*)d_in[2];
    const float* sa_wk = (const float*)d_in[3];
    const float* sa_wv = (const float*)d_in[4];
    const float* sa_wo = (const float*)d_in[5];
    const float* sa_bo = (const float*)d_in[6];
    const float* ca_wq = (const float*)d_in[7];
    const float* ca_wk = (const float*)d_in[8];
    const float* ca_wv = (const float*)d_in[9];
    const float* ca_wo = (const float*)d_in[10];
    const float* ca_bo = (const float*)d_in[11];
    const float* n1_g  = (const float*)d_in[12];
    const float* n1_b  = (const float*)d_in[13];
    const float* n2_g  = (const float*)d_in[14];
    const float* n2_b  = (const float*)d_in[15];
    const float* n3_g  = (const float*)d_in[16];
    const float* n3_b  = (const float*)d_in[17];
    const float* ff_w1 = (const float*)d_in[18];
    const float* ff_b1 = (const float*)d_in[19];
    const float* ff_w2 = (const float*)d_in[20];
    const float* ff_b2 = (const float*)d_in[21];
    float* out = (float*)d_out;

    __half *tmph, *qh, *kh, *vh, *kh2, *vh2, *ath;
    cudaGetSymbolAddress((void**)&tmph, g_tmph);
    cudaGetSymbolAddress((void**)&qh,  g_qh);
    cudaGetSymbolAddress((void**)&kh,  g_kh);
    cudaGetSymbolAddress((void**)&vh,  g_vh);
    cudaGetSymbolAddress((void**)&kh2, g_kh2);
    cudaGetSymbolAddress((void**)&vh2, g_vh2);
    cudaGetSymbolAddress((void**)&ath, g_ath);

    __half *xh, *ctxh, *x1h, *x2h, *ffh;
    cudaGetSymbolAddress((void**)&xh,   g_xh);
    cudaGetSymbolAddress((void**)&ctxh, g_ctxh);
    cudaGetSymbolAddress((void**)&x1h,  g_x1h);
    cudaGetSymbolAddress((void**)&x2h,  g_x2h);
    cudaGetSymbolAddress((void**)&ffh,  g_ffh);

    __half *wqkv, *wqkvca, *wot, *cwot, *w1t, *w2t;
    cudaGetSymbolAddress((void**)&wqkv,   g_wqkv_sa);
    cudaGetSymbolAddress((void**)&wqkvca, g_wqkv_ca);
    cudaGetSymbolAddress((void**)&wot,    g_sa_wot);
    cudaGetSymbolAddress((void**)&cwot,   g_ca_wot);
    cudaGetSymbolAddress((void**)&w1t,    g_w1t);
    cudaGetSymbolAddress((void**)&w2t,    g_w2t);

    cudaFuncSetAttribute(hgemm1_kernel,
                         cudaFuncAttributeMaxDynamicSharedMemorySize, HG1_SMEM);

    cudaStream_t s2;
    cudaStreamCreateWithFlags(&s2, cudaStreamNonBlocking);
    cudaEvent_t evF, evJ, evKV;
    cudaEventCreateWithFlags(&evF,  cudaEventDisableTiming);
    cudaEventCreateWithFlags(&evJ,  cudaEventDisableTiming);
    cudaEventCreateWithFlags(&evKV, cudaEventDisableTiming);

    int nElem = M_ROWS * E;

    dim3 gQKV(3 * E / 128, M_ROWS / 128);   // 24 x 32
    dim3 gKV(2 * E / 128, M_ROWS / 128);    // 16 x 32
    dim3 gE(E / 128, M_ROWS / 128);         // 8 x 32
    dim3 gH(HID / 128, M_ROWS / 128);       // 32 x 32
    dim3 gFA(BATCH * NH, T / 64);

    // Fork: side stream does off-critical preprocessing, then the CA k/v GEMM.
    cudaEventRecord(evF, 0);
    cudaStreamWaitEvent(s2, evF, 0);
    {
        TP8 side;
        side.s[0] = sa_wo; side.d[0] = wot;
        side.s[1] = ca_wq; side.d[1] = wqkvca;
        side.s[2] = ca_wk; side.d[2] = wqkvca + E * E;
        side.s[3] = ca_wv; side.d[3] = wqkvca + 2 * E * E;
        side.s[4] = ca_wo; side.d[4] = cwot;
        transpose64_kernel<<<dim3(E / 64, E / 64, 5), 256, 0, s2>>>(side);
        transpose_ff_kernel<<<dim3(HID / 64, HID / 64, 2), 256, 0, s2>>>(ff_w1, w1t, ff_w2, w2t);
        conv1_h_kernel<<<nElem / 4096, 256, 0, s2>>>(context, ctxh, nElem);
        cudaEventRecord(evJ, s2);
        // CA k/v projection overlaps SA QKV GEMM / FA / wo / LN1 on main.
        hgemm1_kernel<<<gKV, 256, HG1_SMEM, s2>>>(
            ctxh, nullptr, 1 << 30, wqkvca + E * E, nullptr, nullptr,
            kh2, vh2, nullptr, 8, E, 2 * E, E, 0);
        cudaEventRecord(evKV, s2);
    }

    // Main (critical) path: SA q/k/v weights + x convert only.
    {
        TP8 mainp;
        mainp.s[0] = sa_wq; mainp.d[0] = wqkv;
        mainp.s[1] = sa_wk; mainp.d[1] = wqkv + E * E;
        mainp.s[2] = sa_wv; mainp.d[2] = wqkv + 2 * E * E;
        transpose64_kernel<<<dim3(E / 64, E / 64, 3), 256>>>(mainp);
        conv1_h_kernel<<<nElem / 4096, 256>>>(x, xh, nElem);
    }

    // ---- Self-attention ----
    hgemm1_kernel<<<gQKV, 256, HG1_SMEM>>>(xh, nullptr, 1 << 30, wqkv, nullptr, nullptr,
                                           qh, kh, vh, 8, E, 3 * E, E, 0);
    fa_mma_kernel<<<gFA, 128>>>(qh, kh, vh, ath, 1);

    // Join 1: wot ready (side-stream preprocessing done).
    cudaStreamWaitEvent(0, evJ, 0);

    hgemm1_kernel<<<gE, 256, HG1_SMEM>>>(ath, nullptr, 1 << 30, wot, sa_bo, nullptr,
                                         tmph, nullptr, nullptr, 8, E, E, E, 0);
    // LN1: X = x (fp32), out = x1h (fp16, serves as GEMM A and next residual)
    ln_residual_kernel<<<M_ROWS, 256>>>(x, nullptr, tmph, n1_g, n1_b, nullptr, x1h);

    // ---- Cross-attention: q projection only (k/v done on side stream) ----
    hgemm1_kernel<<<gE, 256, HG1_SMEM>>>(x1h, nullptr, 1 << 30, wqkvca, nullptr, nullptr,
                                         qh, nullptr, nullptr, 8, E, E, E, 0);

    // Join 2: CA k/v ready.
    cudaStreamWaitEvent(0, evKV, 0);

    fa_mma_kernel<<<gFA, 128>>>(qh, kh2, vh2, ath, 0);
    hgemm1_kernel<<<gE, 256, HG1_SMEM>>>(ath, nullptr, 1 << 30, cwot, ca_bo, nullptr,
                                         tmph, nullptr, nullptr, 8, E, E, E, 0);
    // LN2: X = x1h (fp16), out = x2h (fp16)
    ln_residual_kernel<<<M_ROWS, 256>>>(nullptr, x1h, tmph, n2_g, n2_b, nullptr, x2h);

    // ---- FFN ----
    hgemm1_kernel<<<gH, 256, HG1_SMEM>>>(x2h, nullptr, 1 << 30, w1t, ff_b1, nullptr,
                                         ffh, nullptr, nullptr, 32, HID, HID, E, 1);
    hgemm1_kernel<<<gE, 256, HG1_SMEM>>>(ffh, nullptr, 1 << 30, w2t, ff_b2, nullptr,
                                         tmph, nullptr, nullptr, 8, E, E, HID, 0);
    // LN3: X = x2h (fp16), out = fp32 harness buffer
    ln_residual_kernel<<<M_ROWS, 256>>>(nullptr, x2h, tmph, n3_g, n3_b, out, nullptr);

    cudaEventDestroy(evF);
    cudaEventDestroy(evJ);
    cudaEventDestroy(evKV);
    cudaStreamDestroy(s2);
}